// round 3
// baseline (speedup 1.0000x reference)
#include <cuda_runtime.h>

#define S_LEN 4096
#define DM 1024
#define NH 16
#define HD 64

#define NEG_INF __int_as_float(0xff800000)

// Scratch (device globals: allocation-free per harness rules)
__device__ float g_Q[NH * S_LEN * HD];   // [h][s][d]
__device__ float g_K[NH * S_LEN * HD];
__device__ float g_V[NH * S_LEN * HD];
__device__ float g_O[S_LEN * DM];        // [s][h*64+d]

// ---------------------------------------------------------------------------
// SGEMM: C = A[M,K] @ B[K,N], M=4096, N=K=1024. 128x128 tile, Kt=8, 256 thr,
// 8x8 micro-tile.
// MODE 0: A = g_O, C = param (row-major, final output).
// MODE 1/2/3: A = param (x), C = g_Q/g_K/g_V in head layout [h][row][d].
// ---------------------------------------------------------------------------
template <int MODE>
__global__ __launch_bounds__(256) void gemm128(const float* __restrict__ Ap,
                                               const float* __restrict__ B,
                                               float* __restrict__ Cp) {
    const int K = DM, N = DM;
    __shared__ float As[8][128];
    __shared__ float Bs[8][128];

    const float* A = (MODE == 0) ? (const float*)g_O : Ap;

    const int tid = threadIdx.x;
    const int row0 = blockIdx.y * 128;
    const int col0 = blockIdx.x * 128;
    const int rb = (tid >> 4) * 8;
    const int cb = (tid & 15) * 8;

    const int ar = tid >> 1;
    const int ak = (tid & 1) * 4;
    const int bk = tid >> 5;
    const int bn = (tid & 31) * 4;

    float acc[8][8] = {};

    for (int k0 = 0; k0 < K; k0 += 8) {
        float4 av = *(const float4*)&A[(row0 + ar) * K + k0 + ak];
        float4 bv = *(const float4*)&B[(k0 + bk) * N + col0 + bn];
        As[ak + 0][ar] = av.x;
        As[ak + 1][ar] = av.y;
        As[ak + 2][ar] = av.z;
        As[ak + 3][ar] = av.w;
        *(float4*)&Bs[bk][bn] = bv;
        __syncthreads();
#pragma unroll
        for (int kk = 0; kk < 8; kk++) {
            float a[8], b[8];
            *(float4*)(a)     = *(float4*)&As[kk][rb];
            *(float4*)(a + 4) = *(float4*)&As[kk][rb + 4];
            *(float4*)(b)     = *(float4*)&Bs[kk][cb];
            *(float4*)(b + 4) = *(float4*)&Bs[kk][cb + 4];
#pragma unroll
            for (int i = 0; i < 8; i++)
#pragma unroll
                for (int j = 0; j < 8; j++) acc[i][j] += a[i] * b[j];
        }
        __syncthreads();
    }

    float* C = (MODE == 1) ? g_Q : (MODE == 2) ? g_K : (MODE == 3) ? g_V : Cp;

#pragma unroll
    for (int i = 0; i < 8; i++) {
        const int r = row0 + rb + i;
#pragma unroll
        for (int j = 0; j < 8; j++) {
            const int c = col0 + cb + j;
            if (MODE == 0) {
                C[r * N + c] = acc[i][j];
            } else {
                const int h = c >> 6;
                const int d = c & 63;
                C[h * (S_LEN * HD) + r * HD + d] = acc[i][j];
            }
        }
    }
}

// ---------------------------------------------------------------------------
// Flash attention, fp32, causal. Br=64 q-rows, Bc=32 k-cols per iteration.
// One CTA per (q-block, head). 256 threads: tx = tid&7 (4 k-cols / 8 d-cols
// each), ty = tid>>3 (2 q-rows each). Row stats (m, l) in registers,
// replicated across the 8 lanes sharing a row group; reductions via
// __shfl_xor_sync(width=8). Static smem only (~42.5 KB) — no attribute call.
// ---------------------------------------------------------------------------
#define QS_STR 65
#define KT_STR 36
#define VS_STR 64
#define PS_STR 33

__global__ __launch_bounds__(256) void attn_kernel() {
    __shared__ float Qs[64 * QS_STR];   // [row][d]
    __shared__ float KsT[64 * KT_STR];  // [d][kcol]  (transposed K tile)
    __shared__ float Vs[32 * VS_STR];   // [kcol][d]
    __shared__ float Ps[64 * PS_STR];   // [row][kcol]

    const int qb  = blockIdx.x;         // 0..63
    const int h   = blockIdx.y;         // 0..15
    const int tid = threadIdx.x;
    const int tx  = tid & 7;            // col group
    const int ty  = tid >> 3;           // row group

    const float* Qh = g_Q + h * (S_LEN * HD);
    const float* Kh = g_K + h * (S_LEN * HD);
    const float* Vh = g_V + h * (S_LEN * HD);

    // Load Q tile (64x64)
#pragma unroll
    for (int l = 0; l < 4; l++) {
        const int idx = tid + l * 256;       // 0..1023
        const int r = idx >> 4;
        const int c4 = (idx & 15) * 4;
        float4 v = *(const float4*)&Qh[(qb * 64 + r) * HD + c4];
        Qs[r * QS_STR + c4 + 0] = v.x;
        Qs[r * QS_STR + c4 + 1] = v.y;
        Qs[r * QS_STR + c4 + 2] = v.z;
        Qs[r * QS_STR + c4 + 3] = v.w;
    }

    float m[2] = {NEG_INF, NEG_INF};
    float l[2] = {0.0f, 0.0f};
    float acc[2][8] = {};

    const int kb_end = 2 * qb + 1;          // inclusive
    for (int kb = 0; kb <= kb_end; kb++) {
        __syncthreads();                    // prior iter's smem reads done
        // Load K (transposed) + V tiles: 32 rows x 64 d each
#pragma unroll
        for (int ld = 0; ld < 2; ld++) {
            const int idx = tid + ld * 256; // 0..511
            const int r = idx >> 4;         // k position 0..31
            const int c4 = (idx & 15) * 4;  // d 0..63
            float4 kv = *(const float4*)&Kh[(kb * 32 + r) * HD + c4];
            KsT[(c4 + 0) * KT_STR + r] = kv.x;
            KsT[(c4 + 1) * KT_STR + r] = kv.y;
            KsT[(c4 + 2) * KT_STR + r] = kv.z;
            KsT[(c4 + 3) * KT_STR + r] = kv.w;
            *(float4*)&Vs[r * VS_STR + c4] =
                *(const float4*)&Vh[(kb * 32 + r) * HD + c4];
        }
        __syncthreads();                    // tiles ready

        // S = Q K^T  (2 rows x 4 cols per thread)
        float s[2][4] = {};
#pragma unroll 8
        for (int d = 0; d < 64; d++) {
            float4 k4 = *(const float4*)&KsT[d * KT_STR + tx * 4];
            float q0 = Qs[(ty * 2 + 0) * QS_STR + d];
            float q1 = Qs[(ty * 2 + 1) * QS_STR + d];
            s[0][0] += q0 * k4.x; s[0][1] += q0 * k4.y;
            s[0][2] += q0 * k4.z; s[0][3] += q0 * k4.w;
            s[1][0] += q1 * k4.x; s[1][1] += q1 * k4.y;
            s[1][2] += q1 * k4.z; s[1][3] += q1 * k4.w;
        }

        const float scale = 0.125f;         // 1/sqrt(64)
        if (kb >= 2 * qb) {                 // diagonal blocks: mask
#pragma unroll
            for (int i = 0; i < 2; i++) {
                const int rg = qb * 64 + ty * 2 + i;
#pragma unroll
                for (int j = 0; j < 4; j++) {
                    const int cg = kb * 32 + tx * 4 + j;
                    s[i][j] = (cg > rg) ? NEG_INF : s[i][j] * scale;
                }
            }
        } else {
#pragma unroll
            for (int i = 0; i < 2; i++)
#pragma unroll
                for (int j = 0; j < 4; j++) s[i][j] *= scale;
        }

        // Online softmax per row (register stats + 8-lane shuffles)
#pragma unroll
        for (int i = 0; i < 2; i++) {
            float pm = fmaxf(fmaxf(s[i][0], s[i][1]), fmaxf(s[i][2], s[i][3]));
#pragma unroll
            for (int o = 1; o < 8; o <<= 1)
                pm = fmaxf(pm, __shfl_xor_sync(0xffffffffu, pm, o, 8));
            const float mx = fmaxf(m[i], pm);
            const float scl = __expf(m[i] - mx);   // exp(-inf-x)=0 first time
            m[i] = mx;

            const int r = ty * 2 + i;
            float psum = 0.0f;
#pragma unroll
            for (int j = 0; j < 4; j++) {
                const float p = __expf(s[i][j] - mx);
                Ps[r * PS_STR + tx * 4 + j] = p;
                psum += p;
            }
#pragma unroll
            for (int o = 1; o < 8; o <<= 1)
                psum += __shfl_xor_sync(0xffffffffu, psum, o, 8);
            l[i] = l[i] * scl + psum;
#pragma unroll
            for (int j = 0; j < 8; j++) acc[i][j] *= scl;
        }
        __syncwarp();                       // Ps visible (row group is warp-local)

        // O += P @ V  (2 rows x 8 d-cols per thread)
#pragma unroll 4
        for (int c = 0; c < 32; c++) {
            float4 va = *(const float4*)&Vs[c * VS_STR + tx * 8];
            float4 vb = *(const float4*)&Vs[c * VS_STR + tx * 8 + 4];
            float p0 = Ps[(ty * 2 + 0) * PS_STR + c];
            float p1 = Ps[(ty * 2 + 1) * PS_STR + c];
            acc[0][0] += p0 * va.x; acc[0][1] += p0 * va.y;
            acc[0][2] += p0 * va.z; acc[0][3] += p0 * va.w;
            acc[0][4] += p0 * vb.x; acc[0][5] += p0 * vb.y;
            acc[0][6] += p0 * vb.z; acc[0][7] += p0 * vb.w;
            acc[1][0] += p1 * va.x; acc[1][1] += p1 * va.y;
            acc[1][2] += p1 * va.z; acc[1][3] += p1 * va.w;
            acc[1][4] += p1 * vb.x; acc[1][5] += p1 * vb.y;
            acc[1][6] += p1 * vb.z; acc[1][7] += p1 * vb.w;
        }
    }

    // Epilogue: normalize, write interleaved [s][h*64+d]
#pragma unroll
    for (int i = 0; i < 2; i++) {
        const int r = ty * 2 + i;
        const float inv = 1.0f / l[i];
        float4 oa, ob;
        oa.x = acc[i][0] * inv; oa.y = acc[i][1] * inv;
        oa.z = acc[i][2] * inv; oa.w = acc[i][3] * inv;
        ob.x = acc[i][4] * inv; ob.y = acc[i][5] * inv;
        ob.z = acc[i][6] * inv; ob.w = acc[i][7] * inv;
        float* dst = &g_O[(qb * 64 + r) * DM + h * HD + tx * 8];
        *(float4*)(dst)     = oa;
        *(float4*)(dst + 4) = ob;
    }
}

// ---------------------------------------------------------------------------
extern "C" void kernel_launch(void* const* d_in, const int* in_sizes, int n_in,
                              void* d_out, int out_size) {
    (void)in_sizes; (void)n_in; (void)out_size;
    const float* x  = (const float*)d_in[0];
    const float* Wq = (const float*)d_in[1];
    const float* Wk = (const float*)d_in[2];
    const float* Wv = (const float*)d_in[3];
    const float* Wo = (const float*)d_in[4];
    float* out = (float*)d_out;

    dim3 gg(DM / 128, S_LEN / 128);  // (8, 32)
    gemm128<1><<<gg, 256>>>(x, Wq, nullptr);
    gemm128<2><<<gg, 256>>>(x, Wk, nullptr);
    gemm128<3><<<gg, 256>>>(x, Wv, nullptr);

    attn_kernel<<<dim3(S_LEN / 64, NH), 256>>>();

    gemm128<0><<<gg, 256>>>(nullptr, Wo, out);
}

// round 4
// speedup vs baseline: 3.1310x; 3.1310x over previous
#include <cuda_runtime.h>

#define S_LEN 4096
#define DM 1024
#define NH 16
#define HD 64
#define NEG_INF __int_as_float(0xff800000)

// Scratch (device globals: allocation-free per harness rules)
__device__ float g_Q[NH * S_LEN * HD];   // [h][s][d]
__device__ float g_K[NH * S_LEN * HD];
__device__ float g_V[NH * S_LEN * HD];
__device__ float g_O[S_LEN * DM];        // [s][h*64+d]

__device__ __forceinline__ unsigned f2tf(float x) {
    unsigned r;
    asm("cvt.rna.tf32.f32 %0, %1;" : "=r"(r) : "f"(x));
    return r;
}

__device__ __forceinline__ void mma_tf32(float& d0, float& d1, float& d2, float& d3,
                                         unsigned a0, unsigned a1, unsigned a2, unsigned a3,
                                         unsigned b0, unsigned b1) {
    asm volatile(
        "mma.sync.aligned.m16n8k8.row.col.f32.tf32.tf32.f32 "
        "{%0,%1,%2,%3}, {%4,%5,%6,%7}, {%8,%9}, {%0,%1,%2,%3};"
        : "+f"(d0), "+f"(d1), "+f"(d2), "+f"(d3)
        : "r"(a0), "r"(a1), "r"(a2), "r"(a3), "r"(b0), "r"(b1));
}

// ---------------------------------------------------------------------------
// tf32 tensor-core GEMM: C = A[4096,1024] @ B[1024,1024].
// Tile 128x128x32, 8 warps (2m x 4n), warp tile 64x32 (4 m16 x 4 n8).
// MODE 0: A = g_O, C = Cp (row-major out).  grid.z = 1, B = W0.
// MODE 1: A = Ap (x), B = W_{q,k,v} by blockIdx.z, C = g_Q/g_K/g_V head layout.
// ---------------------------------------------------------------------------
#define GA_STR 36    // == 4 (mod 32): conflict-free A-frag loads
#define GB_STR 136   // == 8 (mod 32): conflict-free B-frag loads

template <int MODE>
__global__ __launch_bounds__(256) void gemm_tc(const float* __restrict__ Ap,
                                               const float* __restrict__ W0,
                                               const float* __restrict__ W1,
                                               const float* __restrict__ W2,
                                               float* __restrict__ Cp) {
    __shared__ float As[128 * GA_STR];
    __shared__ float Bs[32 * GB_STR];

    const int tid = threadIdx.x;
    const int row0 = blockIdx.y * 128;
    const int col0 = blockIdx.x * 128;

    const float* A = (MODE == 0) ? (const float*)g_O : Ap;
    const float* B = (MODE == 0) ? W0
                     : (blockIdx.z == 0 ? W0 : (blockIdx.z == 1 ? W1 : W2));

    const int lane = tid & 31, wid = tid >> 5;
    const int g = lane >> 2, t = lane & 3;
    const int wm = wid & 1;        // 0..1 -> 64-row block
    const int wn = wid >> 1;       // 0..3 -> 32-col block

    // Loaders
    const int lar = tid >> 1;             // A row 0..127
    const int lac = (tid & 1) * 16;       // A col base (of 32)
    const int lbr = tid >> 3;             // B k-row 0..31
    const int lbc = (tid & 7) * 16;       // B col base (of 128)

    float acc[4][4][4] = {};              // [mi][ni][frag]

    for (int k0 = 0; k0 < DM; k0 += 32) {
#pragma unroll
        for (int i = 0; i < 2; i++) {
            float4 v = *(const float4*)&A[(row0 + lar) * DM + k0 + lac + 8 * i];
            float4 v2 = *(const float4*)&A[(row0 + lar) * DM + k0 + lac + 8 * i + 4];
            float4 w, w2;
            w.x = __uint_as_float(f2tf(v.x));  w.y = __uint_as_float(f2tf(v.y));
            w.z = __uint_as_float(f2tf(v.z));  w.w = __uint_as_float(f2tf(v.w));
            w2.x = __uint_as_float(f2tf(v2.x)); w2.y = __uint_as_float(f2tf(v2.y));
            w2.z = __uint_as_float(f2tf(v2.z)); w2.w = __uint_as_float(f2tf(v2.w));
            *(float4*)&As[lar * GA_STR + lac + 8 * i] = w;
            *(float4*)&As[lar * GA_STR + lac + 8 * i + 4] = w2;
        }
#pragma unroll
        for (int i = 0; i < 4; i++) {
            float4 v = *(const float4*)&B[(k0 + lbr) * DM + col0 + lbc + 4 * i];
            float4 w;
            w.x = __uint_as_float(f2tf(v.x));  w.y = __uint_as_float(f2tf(v.y));
            w.z = __uint_as_float(f2tf(v.z));  w.w = __uint_as_float(f2tf(v.w));
            *(float4*)&Bs[lbr * GB_STR + lbc + 4 * i] = w;
        }
        __syncthreads();

#pragma unroll
        for (int kt = 0; kt < 4; kt++) {
            const int kk = kt * 8;
            unsigned a[4][4], b[4][2];
#pragma unroll
            for (int mi = 0; mi < 4; mi++) {
                const float* base = &As[(wm * 64 + mi * 16) * GA_STR + kk];
                a[mi][0] = __float_as_uint(base[g * GA_STR + t]);
                a[mi][1] = __float_as_uint(base[(g + 8) * GA_STR + t]);
                a[mi][2] = __float_as_uint(base[g * GA_STR + t + 4]);
                a[mi][3] = __float_as_uint(base[(g + 8) * GA_STR + t + 4]);
            }
#pragma unroll
            for (int ni = 0; ni < 4; ni++) {
                const float* base = &Bs[kk * GB_STR + wn * 32 + ni * 8 + g];
                b[ni][0] = __float_as_uint(base[t * GB_STR]);
                b[ni][1] = __float_as_uint(base[(t + 4) * GB_STR]);
            }
#pragma unroll
            for (int mi = 0; mi < 4; mi++)
#pragma unroll
                for (int ni = 0; ni < 4; ni++)
                    mma_tf32(acc[mi][ni][0], acc[mi][ni][1], acc[mi][ni][2], acc[mi][ni][3],
                             a[mi][0], a[mi][1], a[mi][2], a[mi][3],
                             b[ni][0], b[ni][1]);
        }
        __syncthreads();
    }

    float* C = (MODE == 0) ? Cp
               : (blockIdx.z == 0 ? g_Q : (blockIdx.z == 1 ? g_K : g_V));

#pragma unroll
    for (int mi = 0; mi < 4; mi++) {
        const int r0 = row0 + wm * 64 + mi * 16 + g;
#pragma unroll
        for (int ni = 0; ni < 4; ni++) {
            const int c = col0 + wn * 32 + ni * 8 + 2 * t;
            if (MODE == 0) {
                *(float2*)&C[r0 * DM + c] = make_float2(acc[mi][ni][0], acc[mi][ni][1]);
                *(float2*)&C[(r0 + 8) * DM + c] = make_float2(acc[mi][ni][2], acc[mi][ni][3]);
            } else {
                const int h = c >> 6;
                const int d = c & 63;
                float* dst = &C[h * (S_LEN * HD) + r0 * HD + d];
                *(float2*)dst = make_float2(acc[mi][ni][0], acc[mi][ni][1]);
                *(float2*)(dst + 8 * HD) = make_float2(acc[mi][ni][2], acc[mi][ni][3]);
            }
        }
    }
}

// ---------------------------------------------------------------------------
// Flash attention, tf32 tensor cores, causal. Br=64, Bc=32. One CTA per
// (q-block, head). 8 warps as 4(m) x 2(n). S and PV on mma.sync; online
// softmax stats in registers (width-4 shuffles + 2-warp smem combine).
// Static smem ~45.6 KB.
// ---------------------------------------------------------------------------
#define QS 68   // == 4 (mod 32)
#define KS 68
#define VS 36
#define PS 36

__global__ __launch_bounds__(256) void attn_tc() {
    __shared__ float Qs[64 * QS];     // [row][d]
    __shared__ float Ks[32 * KS];     // [kpos][d]
    __shared__ float VsT[64 * VS];    // [d][kpos]
    __shared__ float Ps[64 * PS];     // [row][kpos]
    __shared__ float redm[2][64];
    __shared__ float reds[2][64];

    const int qb = blockIdx.x;        // 0..63
    const int h  = blockIdx.y;        // 0..15
    const int tid = threadIdx.x;
    const int lane = tid & 31, wid = tid >> 5;
    const int g = lane >> 2, t = lane & 3;
    const int wm = wid & 3;           // 0..3 -> 16-row block
    const int wn = wid >> 2;          // 0..1 -> 16-col (S) / 32-col (O) block

    const float* Qh = g_Q + h * (S_LEN * HD);
    const float* Kh = g_K + h * (S_LEN * HD);
    const float* Vh = g_V + h * (S_LEN * HD);

    // Load Q (64x64), scaled by 1/sqrt(64) and tf32-rounded
#pragma unroll
    for (int l = 0; l < 4; l++) {
        const int idx = tid + l * 256;
        const int r = idx >> 4;
        const int c4 = (idx & 15) * 4;
        float4 v = *(const float4*)&Qh[(qb * 64 + r) * HD + c4];
        float4 w;
        w.x = __uint_as_float(f2tf(v.x * 0.125f));
        w.y = __uint_as_float(f2tf(v.y * 0.125f));
        w.z = __uint_as_float(f2tf(v.z * 0.125f));
        w.w = __uint_as_float(f2tf(v.w * 0.125f));
        *(float4*)&Qs[r * QS + c4] = w;
    }

    float m0 = NEG_INF, m1 = NEG_INF;
    float l0 = 0.0f, l1 = 0.0f;
    float o[4][4] = {};               // [ni][frag]

    const int r0 = wm * 16 + g;       // this thread's local rows
    const int r1 = r0 + 8;

    const int kb_end = 2 * qb + 1;
    for (int kb = 0; kb <= kb_end; kb++) {
        __syncthreads();   // prior iter done reading Ks/VsT/Ps
        // Load K (32x64) and V (transposed) tiles
#pragma unroll
        for (int l = 0; l < 2; l++) {
            const int idx = tid + l * 256;     // 0..511
            const int r = idx >> 4;            // kpos 0..31
            const int c4 = (idx & 15) * 4;     // d
            float4 kv = *(const float4*)&Kh[(kb * 32 + r) * HD + c4];
            float4 kw;
            kw.x = __uint_as_float(f2tf(kv.x));
            kw.y = __uint_as_float(f2tf(kv.y));
            kw.z = __uint_as_float(f2tf(kv.z));
            kw.w = __uint_as_float(f2tf(kv.w));
            *(float4*)&Ks[r * KS + c4] = kw;
            float4 vv = *(const float4*)&Vh[(kb * 32 + r) * HD + c4];
            VsT[(c4 + 0) * VS + r] = __uint_as_float(f2tf(vv.x));
            VsT[(c4 + 1) * VS + r] = __uint_as_float(f2tf(vv.y));
            VsT[(c4 + 2) * VS + r] = __uint_as_float(f2tf(vv.z));
            VsT[(c4 + 3) * VS + r] = __uint_as_float(f2tf(vv.w));
        }
        __syncthreads();

        // S = Q K^T : warp rows [wm*16,+16), cols [wn*16,+16) (2 n8 tiles)
        float s[2][4] = {};
#pragma unroll
        for (int kt = 0; kt < 8; kt++) {
            const int kk = kt * 8;
            const float* abase = &Qs[(wm * 16) * QS + kk];
            unsigned a0 = __float_as_uint(abase[g * QS + t]);
            unsigned a1 = __float_as_uint(abase[(g + 8) * QS + t]);
            unsigned a2 = __float_as_uint(abase[g * QS + t + 4]);
            unsigned a3 = __float_as_uint(abase[(g + 8) * QS + t + 4]);
#pragma unroll
            for (int ni = 0; ni < 2; ni++) {
                const float* bbase = &Ks[(wn * 16 + ni * 8 + g) * KS + kk];
                unsigned b0 = __float_as_uint(bbase[t]);
                unsigned b1 = __float_as_uint(bbase[t + 4]);
                mma_tf32(s[ni][0], s[ni][1], s[ni][2], s[ni][3],
                         a0, a1, a2, a3, b0, b1);
            }
        }

        // Causal mask (only needed on the two diagonal 32-blocks)
        if (kb >= 2 * qb) {
            const int rg0 = qb * 64 + r0;
            const int rg1 = qb * 64 + r1;
#pragma unroll
            for (int ni = 0; ni < 2; ni++) {
                const int cb = kb * 32 + wn * 16 + ni * 8 + 2 * t;
                if (cb > rg0) s[ni][0] = NEG_INF;
                if (cb + 1 > rg0) s[ni][1] = NEG_INF;
                if (cb > rg1) s[ni][2] = NEG_INF;
                if (cb + 1 > rg1) s[ni][3] = NEG_INF;
            }
        }

        // Row max: intra-warp (4 lanes) then 2-warp smem combine
        float pm0 = fmaxf(fmaxf(s[0][0], s[0][1]), fmaxf(s[1][0], s[1][1]));
        float pm1 = fmaxf(fmaxf(s[0][2], s[0][3]), fmaxf(s[1][2], s[1][3]));
#pragma unroll
        for (int off = 1; off < 4; off <<= 1) {
            pm0 = fmaxf(pm0, __shfl_xor_sync(0xffffffffu, pm0, off, 4));
            pm1 = fmaxf(pm1, __shfl_xor_sync(0xffffffffu, pm1, off, 4));
        }
        if (t == 0) {
            redm[wn][r0] = pm0;
            redm[wn][r1] = pm1;
        }
        __syncthreads();
        const float mx0 = fmaxf(m0, fmaxf(redm[0][r0], redm[1][r0]));
        const float mx1 = fmaxf(m1, fmaxf(redm[0][r1], redm[1][r1]));
        const float scl0 = __expf(m0 - mx0);   // exp(-inf - x) = 0 first time
        const float scl1 = __expf(m1 - mx1);
        m0 = mx0; m1 = mx1;

        // P = exp(S - m), store tf32-rounded to smem, partial row sums
        float ps0 = 0.0f, ps1 = 0.0f;
#pragma unroll
        for (int ni = 0; ni < 2; ni++) {
            const int cb = wn * 16 + ni * 8 + 2 * t;
            float p0 = __expf(s[ni][0] - mx0);
            float p1 = __expf(s[ni][1] - mx0);
            float p2 = __expf(s[ni][2] - mx1);
            float p3 = __expf(s[ni][3] - mx1);
            ps0 += p0 + p1;
            ps1 += p2 + p3;
            *(float2*)&Ps[r0 * PS + cb] = make_float2(__uint_as_float(f2tf(p0)),
                                                      __uint_as_float(f2tf(p1)));
            *(float2*)&Ps[r1 * PS + cb] = make_float2(__uint_as_float(f2tf(p2)),
                                                      __uint_as_float(f2tf(p3)));
        }
#pragma unroll
        for (int off = 1; off < 4; off <<= 1) {
            ps0 += __shfl_xor_sync(0xffffffffu, ps0, off, 4);
            ps1 += __shfl_xor_sync(0xffffffffu, ps1, off, 4);
        }
        if (t == 0) {
            reds[wn][r0] = ps0;
            reds[wn][r1] = ps1;
        }
        __syncthreads();   // Ps + reds visible
        l0 = l0 * scl0 + reds[0][r0] + reds[1][r0];
        l1 = l1 * scl1 + reds[0][r1] + reds[1][r1];

        // Rescale O accumulators
#pragma unroll
        for (int ni = 0; ni < 4; ni++) {
            o[ni][0] *= scl0; o[ni][1] *= scl0;
            o[ni][2] *= scl1; o[ni][3] *= scl1;
        }

        // O += P @ V : warp rows [wm*16,+16), O cols [wn*32,+32) (4 n8 tiles)
#pragma unroll
        for (int kt = 0; kt < 4; kt++) {
            const int kk = kt * 8;
            const float* abase = &Ps[(wm * 16) * PS + kk];
            unsigned a0 = __float_as_uint(abase[g * PS + t]);
            unsigned a1 = __float_as_uint(abase[(g + 8) * PS + t]);
            unsigned a2 = __float_as_uint(abase[g * PS + t + 4]);
            unsigned a3 = __float_as_uint(abase[(g + 8) * PS + t + 4]);
#pragma unroll
            for (int ni = 0; ni < 4; ni++) {
                const float* bbase = &VsT[(wn * 32 + ni * 8 + g) * VS + kk];
                unsigned b0 = __float_as_uint(bbase[t]);
                unsigned b1 = __float_as_uint(bbase[t + 4]);
                mma_tf32(o[ni][0], o[ni][1], o[ni][2], o[ni][3],
                         a0, a1, a2, a3, b0, b1);
            }
        }
    }

    // Epilogue: normalize, write interleaved [s][h*64+d]
    const float inv0 = 1.0f / l0;
    const float inv1 = 1.0f / l1;
    const int q0 = qb * 64 + r0;
    const int q1 = qb * 64 + r1;
#pragma unroll
    for (int ni = 0; ni < 4; ni++) {
        const int c = h * HD + wn * 32 + ni * 8 + 2 * t;
        *(float2*)&g_O[q0 * DM + c] = make_float2(o[ni][0] * inv0, o[ni][1] * inv0);
        *(float2*)&g_O[q1 * DM + c] = make_float2(o[ni][2] * inv1, o[ni][3] * inv1);
    }
}

// ---------------------------------------------------------------------------
extern "C" void kernel_launch(void* const* d_in, const int* in_sizes, int n_in,
                              void* d_out, int out_size) {
    (void)in_sizes; (void)n_in; (void)out_size;
    const float* x  = (const float*)d_in[0];
    const float* Wq = (const float*)d_in[1];
    const float* Wk = (const float*)d_in[2];
    const float* Wv = (const float*)d_in[3];
    const float* Wo = (const float*)d_in[4];
    float* out = (float*)d_out;

    // QKV projections: one launch, blockIdx.z selects q/k/v
    gemm_tc<1><<<dim3(DM / 128, S_LEN / 128, 3), 256>>>(x, Wq, Wk, Wv, nullptr);

    attn_tc<<<dim3(S_LEN / 64, NH), 256>>>();

    gemm_tc<0><<<dim3(DM / 128, S_LEN / 128, 1), 256>>>(nullptr, Wo, nullptr, nullptr, out);
}

// round 5
// speedup vs baseline: 5.2813x; 1.6868x over previous
#include <cuda_runtime.h>

#define S_LEN 4096
#define DM 1024
#define NH 16
#define HD 64
#define NEG_INF __int_as_float(0xff800000)

// Scratch (device globals: allocation-free per harness rules)
__device__ float g_Q[NH * S_LEN * HD];   // [h][s][d]  tf32-rounded, pre-scaled 0.125
__device__ float g_K[NH * S_LEN * HD];   // tf32-rounded
__device__ float g_V[NH * S_LEN * HD];   // tf32-rounded
__device__ float g_O[S_LEN * DM];        // [s][h*64+d] tf32-rounded
__device__ float g_Xr[S_LEN * DM];       // tf32-rounded x
__device__ float g_Wr[4][DM * DM];       // tf32-rounded Wq,Wk,Wv,Wo

__device__ __forceinline__ unsigned f2tf(float x) {
    unsigned r;
    asm("cvt.rna.tf32.f32 %0, %1;" : "=r"(r) : "f"(x));
    return r;
}
__device__ __forceinline__ float f2tff(float x) { return __uint_as_float(f2tf(x)); }

__device__ __forceinline__ void mma_tf32(float& d0, float& d1, float& d2, float& d3,
                                         unsigned a0, unsigned a1, unsigned a2, unsigned a3,
                                         unsigned b0, unsigned b1) {
    asm volatile(
        "mma.sync.aligned.m16n8k8.row.col.f32.tf32.tf32.f32 "
        "{%0,%1,%2,%3}, {%4,%5,%6,%7}, {%8,%9}, {%0,%1,%2,%3};"
        : "+f"(d0), "+f"(d1), "+f"(d2), "+f"(d3)
        : "r"(a0), "r"(a1), "r"(a2), "r"(a3), "r"(b0), "r"(b1));
}

__device__ __forceinline__ void cp16(void* smem_dst, const void* gsrc) {
    unsigned d = (unsigned)__cvta_generic_to_shared(smem_dst);
    asm volatile("cp.async.ca.shared.global [%0], [%1], 16;" :: "r"(d), "l"(gsrc));
}
__device__ __forceinline__ void cp_commit() {
    asm volatile("cp.async.commit_group;");
}
template <int N>
__device__ __forceinline__ void cp_wait() {
    asm volatile("cp.async.wait_group %0;" :: "n"(N));
}

// ---------------------------------------------------------------------------
// Prepass: tf32-round x and the four weight matrices into scratch.
// ---------------------------------------------------------------------------
__global__ __launch_bounds__(256) void prepass(const float* __restrict__ x,
                                               const float* __restrict__ wq,
                                               const float* __restrict__ wk,
                                               const float* __restrict__ wv,
                                               const float* __restrict__ wo) {
    const int XN = S_LEN * DM / 4;   // float4 count for x
    const int WN = DM * DM / 4;      // per weight
    int i = blockIdx.x * blockDim.x + threadIdx.x;
    const float4* src;
    float4* dst;
    int j;
    if (i < XN) {
        src = (const float4*)x; dst = (float4*)g_Xr; j = i;
    } else {
        int k = i - XN;
        int w = k / WN; j = k % WN;
        const float* s = (w == 0) ? wq : (w == 1) ? wk : (w == 2) ? wv : wo;
        src = (const float4*)s; dst = (float4*)g_Wr[w];
    }
    float4 v = src[j];
    v.x = f2tff(v.x); v.y = f2tff(v.y); v.z = f2tff(v.z); v.w = f2tff(v.w);
    dst[j] = v;
}

// ---------------------------------------------------------------------------
// tf32 tensor-core GEMM, cp.async double-buffered, BK=16.
// MODE 0: A=g_O, B=g_Wr[3], C=Cp (row-major final output, fp32).
// MODE 1: A=g_Xr, B=g_Wr[z], C=g_Q/g_K/g_V head layout, tf32-rounded
//         (Q additionally scaled by 0.125).
// Tile 128x128x16, 8 warps (2m x 4n), warp 64x32.
// ---------------------------------------------------------------------------
#define AS_STR 20    // 128 rows x (16+4)
#define BS_STR 136   // 16 rows  x (128+8)

template <int MODE>
__global__ __launch_bounds__(256) void gemm_tc(float* __restrict__ Cp) {
    __shared__ float As[2][128 * AS_STR];
    __shared__ float Bs[2][16 * BS_STR];

    const int tid = threadIdx.x;
    const int row0 = blockIdx.y * 128;
    const int col0 = blockIdx.x * 128;
    const int z = (MODE == 0) ? 3 : blockIdx.z;

    const float* A = (MODE == 0) ? (const float*)g_O : (const float*)g_Xr;
    const float* B = g_Wr[z];

    const int lane = tid & 31, wid = tid >> 5;
    const int g = lane >> 2, t = lane & 3;
    const int wm = wid & 1;
    const int wn = wid >> 1;

    // cp.async loaders: A tile 128x16 (512 16B segs), B tile 16x128 (512 segs)
    const int ar = tid >> 2, ac4 = (tid & 3) * 4;          // +256: rows 64..127
    const int br = tid >> 5, bc4 = (tid & 31) * 4;         // +256: rows 8..15

    float acc[4][4][4] = {};

#define LOAD_TILE(k0, buf)                                                    \
    do {                                                                      \
        cp16(&As[buf][ar * AS_STR + ac4], &A[(row0 + ar) * DM + (k0) + ac4]); \
        cp16(&As[buf][(ar + 64) * AS_STR + ac4],                              \
             &A[(row0 + ar + 64) * DM + (k0) + ac4]);                         \
        cp16(&Bs[buf][br * BS_STR + bc4], &B[((k0) + br) * DM + col0 + bc4]); \
        cp16(&Bs[buf][(br + 8) * BS_STR + bc4],                               \
             &B[((k0) + br + 8) * DM + col0 + bc4]);                          \
        cp_commit();                                                          \
    } while (0)

    LOAD_TILE(0, 0);

    for (int it = 0; it < 64; it++) {
        const int buf = it & 1;
        if (it + 1 < 64) {
            LOAD_TILE((it + 1) * 16, buf ^ 1);
            cp_wait<1>();
        } else {
            cp_wait<0>();
        }
        __syncthreads();

#pragma unroll
        for (int kt = 0; kt < 2; kt++) {
            const int kk = kt * 8;
            unsigned a[4][4], b[4][2];
#pragma unroll
            for (int mi = 0; mi < 4; mi++) {
                const float* base = &As[buf][(wm * 64 + mi * 16) * AS_STR + kk];
                a[mi][0] = __float_as_uint(base[g * AS_STR + t]);
                a[mi][1] = __float_as_uint(base[(g + 8) * AS_STR + t]);
                a[mi][2] = __float_as_uint(base[g * AS_STR + t + 4]);
                a[mi][3] = __float_as_uint(base[(g + 8) * AS_STR + t + 4]);
            }
#pragma unroll
            for (int ni = 0; ni < 4; ni++) {
                const float* base = &Bs[buf][kk * BS_STR + wn * 32 + ni * 8 + g];
                b[ni][0] = __float_as_uint(base[t * BS_STR]);
                b[ni][1] = __float_as_uint(base[(t + 4) * BS_STR]);
            }
#pragma unroll
            for (int mi = 0; mi < 4; mi++)
#pragma unroll
                for (int ni = 0; ni < 4; ni++)
                    mma_tf32(acc[mi][ni][0], acc[mi][ni][1], acc[mi][ni][2], acc[mi][ni][3],
                             a[mi][0], a[mi][1], a[mi][2], a[mi][3],
                             b[ni][0], b[ni][1]);
        }
        __syncthreads();
    }
#undef LOAD_TILE

    if (MODE == 0) {
#pragma unroll
        for (int mi = 0; mi < 4; mi++) {
            const int r0 = row0 + wm * 64 + mi * 16 + g;
#pragma unroll
            for (int ni = 0; ni < 4; ni++) {
                const int c = col0 + wn * 32 + ni * 8 + 2 * t;
                *(float2*)&Cp[r0 * DM + c] = make_float2(acc[mi][ni][0], acc[mi][ni][1]);
                *(float2*)&Cp[(r0 + 8) * DM + c] = make_float2(acc[mi][ni][2], acc[mi][ni][3]);
            }
        }
    } else {
        float* C = (z == 0) ? g_Q : (z == 1) ? g_K : g_V;
        const float sc = (z == 0) ? 0.125f : 1.0f;
#pragma unroll
        for (int mi = 0; mi < 4; mi++) {
            const int r0 = row0 + wm * 64 + mi * 16 + g;
#pragma unroll
            for (int ni = 0; ni < 4; ni++) {
                const int c = col0 + wn * 32 + ni * 8 + 2 * t;
                const int hh = c >> 6, d = c & 63;
                float* dst = &C[hh * (S_LEN * HD) + r0 * HD + d];
                *(float2*)dst = make_float2(f2tff(acc[mi][ni][0] * sc),
                                            f2tff(acc[mi][ni][1] * sc));
                *(float2*)(dst + 8 * HD) = make_float2(f2tff(acc[mi][ni][2] * sc),
                                                       f2tff(acc[mi][ni][3] * sc));
            }
        }
    }
}

// ---------------------------------------------------------------------------
// Warp-specialized flash attention, tf32 tensor cores, causal. Br=64, Bc=32.
// Warps 0-3: consumers (warp w owns rows [16w,16w+16), all 32 S-cols, all 64
// O-cols). Row stats warp-local (width-4 shuffles). Warps 4-7: producers —
// cp.async double-buffered K/V tiles. Q fragments held in registers.
// 2 __syncthreads + 1 __syncwarp per KV iteration. 44 KB static smem.
// ---------------------------------------------------------------------------
#define KS2 68   // 32 x (64+4)
#define VS2 72   // 32 x (64+8)
#define PS2 36   // 64 x (32+4)

__global__ __launch_bounds__(256) void attn_tc() {
    __shared__ float Ks[2][32 * KS2];
    __shared__ float Vs[2][32 * VS2];
    __shared__ float Ps[64 * PS2];

    const int qb = (int)gridDim.x - 1 - (int)blockIdx.x;  // long CTAs first
    const int h  = blockIdx.y;
    const int tid = threadIdx.x;
    const int lane = tid & 31, wid = tid >> 5;
    const int g = lane >> 2, t = lane & 3;
    const bool producer = (wid >= 4);
    const int wm = wid & 3;

    const float* Qh = g_Q + h * (S_LEN * HD);
    const float* Kh = g_K + h * (S_LEN * HD);
    const float* Vh = g_V + h * (S_LEN * HD);

    const int kb_end = 2 * qb + 1;

#define LOAD_KV(kb, buf)                                                      \
    do {                                                                      \
        const int t2 = tid - 128;                                             \
        _Pragma("unroll")                                                     \
        for (int j = 0; j < 4; j++) {                                         \
            const int seg = t2 + j * 128;                                     \
            const int r = seg >> 4, c4 = (seg & 15) * 4;                      \
            cp16(&Ks[buf][r * KS2 + c4], &Kh[((kb) * 32 + r) * HD + c4]);     \
            cp16(&Vs[buf][r * VS2 + c4], &Vh[((kb) * 32 + r) * HD + c4]);     \
        }                                                                     \
        cp_commit();                                                          \
    } while (0)

    if (producer) LOAD_KV(0, 0);

    // Consumers: Q fragments in registers for the whole loop (pre-scaled,
    // pre-rounded by the QKV GEMM epilogue).
    unsigned qf[8][4];
    if (!producer) {
        const int q0 = qb * 64 + wm * 16 + g;
#pragma unroll
        for (int kt = 0; kt < 8; kt++) {
            const int kk = kt * 8;
            qf[kt][0] = __float_as_uint(Qh[q0 * HD + kk + t]);
            qf[kt][1] = __float_as_uint(Qh[(q0 + 8) * HD + kk + t]);
            qf[kt][2] = __float_as_uint(Qh[q0 * HD + kk + t + 4]);
            qf[kt][3] = __float_as_uint(Qh[(q0 + 8) * HD + kk + t + 4]);
        }
    }

    float m0 = NEG_INF, m1 = NEG_INF;
    float l0 = 0.0f, l1 = 0.0f;
    float o[8][4] = {};

    for (int kb = 0; kb <= kb_end; kb++) {
        const int buf = kb & 1;
        if (producer) {
            if (kb < kb_end) {
                LOAD_KV(kb + 1, buf ^ 1);
                cp_wait<1>();
            } else {
                cp_wait<0>();
            }
        }
        __syncthreads();    // tiles[buf] ready; prior buf^1 reads finished

        if (!producer) {
            // ---- S = Q K^T : 16 rows x 32 cols per warp ----
            float s[4][4] = {};
#pragma unroll
            for (int kt = 0; kt < 8; kt++) {
                const int kk = kt * 8;
#pragma unroll
                for (int ni = 0; ni < 4; ni++) {
                    const float* bb = &Ks[buf][(ni * 8 + g) * KS2 + kk];
                    mma_tf32(s[ni][0], s[ni][1], s[ni][2], s[ni][3],
                             qf[kt][0], qf[kt][1], qf[kt][2], qf[kt][3],
                             __float_as_uint(bb[t]), __float_as_uint(bb[t + 4]));
                }
            }

            // ---- causal mask (diagonal 32-blocks only) ----
            if (kb >= 2 * qb) {
                const int rg0 = qb * 64 + wm * 16 + g;
                const int rg1 = rg0 + 8;
#pragma unroll
                for (int ni = 0; ni < 4; ni++) {
                    const int cb = kb * 32 + ni * 8 + 2 * t;
                    if (cb > rg0) s[ni][0] = NEG_INF;
                    if (cb + 1 > rg0) s[ni][1] = NEG_INF;
                    if (cb > rg1) s[ni][2] = NEG_INF;
                    if (cb + 1 > rg1) s[ni][3] = NEG_INF;
                }
            }

            // ---- online softmax, fully warp-local ----
            float pm0 = fmaxf(fmaxf(s[0][0], s[0][1]), fmaxf(s[1][0], s[1][1]));
            pm0 = fmaxf(pm0, fmaxf(fmaxf(s[2][0], s[2][1]), fmaxf(s[3][0], s[3][1])));
            float pm1 = fmaxf(fmaxf(s[0][2], s[0][3]), fmaxf(s[1][2], s[1][3]));
            pm1 = fmaxf(pm1, fmaxf(fmaxf(s[2][2], s[2][3]), fmaxf(s[3][2], s[3][3])));
#pragma unroll
            for (int off = 1; off < 4; off <<= 1) {
                pm0 = fmaxf(pm0, __shfl_xor_sync(0xffffffffu, pm0, off, 4));
                pm1 = fmaxf(pm1, __shfl_xor_sync(0xffffffffu, pm1, off, 4));
            }
            const float mx0 = fmaxf(m0, pm0);
            const float mx1 = fmaxf(m1, pm1);
            const float scl0 = __expf(m0 - mx0);
            const float scl1 = __expf(m1 - mx1);
            m0 = mx0; m1 = mx1;

            const int r0 = wm * 16 + g;
            const int r1 = r0 + 8;
            float ps0 = 0.0f, ps1 = 0.0f;
#pragma unroll
            for (int ni = 0; ni < 4; ni++) {
                const int cb = ni * 8 + 2 * t;
                float p0 = __expf(s[ni][0] - mx0);
                float p1 = __expf(s[ni][1] - mx0);
                float p2 = __expf(s[ni][2] - mx1);
                float p3 = __expf(s[ni][3] - mx1);
                ps0 += p0 + p1;
                ps1 += p2 + p3;
                *(float2*)&Ps[r0 * PS2 + cb] = make_float2(f2tff(p0), f2tff(p1));
                *(float2*)&Ps[r1 * PS2 + cb] = make_float2(f2tff(p2), f2tff(p3));
            }
#pragma unroll
            for (int off = 1; off < 4; off <<= 1) {
                ps0 += __shfl_xor_sync(0xffffffffu, ps0, off, 4);
                ps1 += __shfl_xor_sync(0xffffffffu, ps1, off, 4);
            }
            l0 = l0 * scl0 + ps0;
            l1 = l1 * scl1 + ps1;

#pragma unroll
            for (int ni = 0; ni < 8; ni++) {
                o[ni][0] *= scl0; o[ni][1] *= scl0;
                o[ni][2] *= scl1; o[ni][3] *= scl1;
            }
            __syncwarp();    // Ps rows are warp-local: warp barrier suffices

            // ---- O += P V : 16 rows x 64 cols per warp ----
#pragma unroll
            for (int kt = 0; kt < 4; kt++) {
                const int kk = kt * 8;
                const float* ab = &Ps[(wm * 16) * PS2 + kk];
                unsigned a0 = __float_as_uint(ab[g * PS2 + t]);
                unsigned a1 = __float_as_uint(ab[(g + 8) * PS2 + t]);
                unsigned a2 = __float_as_uint(ab[g * PS2 + t + 4]);
                unsigned a3 = __float_as_uint(ab[(g + 8) * PS2 + t + 4]);
#pragma unroll
                for (int ni = 0; ni < 8; ni++) {
                    const float* bb = &Vs[buf][ni * 8 + g];
                    mma_tf32(o[ni][0], o[ni][1], o[ni][2], o[ni][3],
                             a0, a1, a2, a3,
                             __float_as_uint(bb[(kk + t) * VS2]),
                             __float_as_uint(bb[(kk + t + 4) * VS2]));
                }
            }
        }
        __syncthreads();    // all reads of tiles[buf] + Ps done
    }
#undef LOAD_KV

    if (!producer) {
        const float inv0 = 1.0f / l0;
        const float inv1 = 1.0f / l1;
        const int q0 = qb * 64 + wm * 16 + g;
#pragma unroll
        for (int ni = 0; ni < 8; ni++) {
            const int c = h * HD + ni * 8 + 2 * t;
            *(float2*)&g_O[q0 * DM + c] =
                make_float2(f2tff(o[ni][0] * inv0), f2tff(o[ni][1] * inv0));
            *(float2*)&g_O[(q0 + 8) * DM + c] =
                make_float2(f2tff(o[ni][2] * inv1), f2tff(o[ni][3] * inv1));
        }
    }
}

// ---------------------------------------------------------------------------
extern "C" void kernel_launch(void* const* d_in, const int* in_sizes, int n_in,
                              void* d_out, int out_size) {
    (void)in_sizes; (void)n_in; (void)out_size;
    const float* x  = (const float*)d_in[0];
    const float* Wq = (const float*)d_in[1];
    const float* Wk = (const float*)d_in[2];
    const float* Wv = (const float*)d_in[3];
    const float* Wo = (const float*)d_in[4];
    float* out = (float*)d_out;

    const int n4 = (S_LEN * DM + 4 * DM * DM) / 4;   // 2M float4s
    prepass<<<n4 / 256, 256>>>(x, Wq, Wk, Wv, Wo);

    gemm_tc<1><<<dim3(DM / 128, S_LEN / 128, 3), 256>>>(nullptr);

    attn_tc<<<dim3(S_LEN / 64, NH), 256>>>();

    gemm_tc<0><<<dim3(DM / 128, S_LEN / 128, 1), 256>>>(out);
}

// round 8
// speedup vs baseline: 9.0408x; 1.7118x over previous
#include <cuda_runtime.h>
#include <cuda_fp16.h>
#include <cstdint>

#define S_LEN 4096
#define DM 1024
#define NH 16
#define HD 64
#define NEG_INF __int_as_float(0xff800000)

// Scratch (device globals: allocation-free per harness rules). All fp16.
__device__ __half g_Q[NH * S_LEN * HD];  // [h][s][d], pre-scaled 0.125
__device__ __half g_K[NH * S_LEN * HD];
__device__ __half g_V[NH * S_LEN * HD];
__device__ __half g_O[S_LEN * DM];       // [s][h*64+d]
__device__ __half g_Xr[S_LEN * DM];      // x in fp16
__device__ __half g_Wr[4][DM * DM];      // W^T: [n][k], k contiguous

__device__ __forceinline__ void mma_f16(float& d0, float& d1, float& d2, float& d3,
                                        unsigned a0, unsigned a1, unsigned a2, unsigned a3,
                                        unsigned b0, unsigned b1) {
    asm volatile(
        "mma.sync.aligned.m16n8k16.row.col.f32.f16.f16.f32 "
        "{%0,%1,%2,%3}, {%4,%5,%6,%7}, {%8,%9}, {%0,%1,%2,%3};"
        : "+f"(d0), "+f"(d1), "+f"(d2), "+f"(d3)
        : "r"(a0), "r"(a1), "r"(a2), "r"(a3), "r"(b0), "r"(b1));
}

__device__ __forceinline__ void cp16(void* smem_dst, const void* gsrc) {
    unsigned d = (unsigned)__cvta_generic_to_shared(smem_dst);
    asm volatile("cp.async.cg.shared.global [%0], [%1], 16;" :: "r"(d), "l"(gsrc));
}
__device__ __forceinline__ void cp_commit() { asm volatile("cp.async.commit_group;"); }
template <int N>
__device__ __forceinline__ void cp_wait() {
    asm volatile("cp.async.wait_group %0;" :: "n"(N));
}

__device__ __forceinline__ unsigned pack2(float a, float b) {
    __half2 h = __floats2half2_rn(a, b);
    return *(unsigned*)&h;
}

// ---------------------------------------------------------------------------
// Prepass A: x -> fp16.
// ---------------------------------------------------------------------------
__global__ __launch_bounds__(256) void prepass_x(const float* __restrict__ x) {
    int i = blockIdx.x * 256 + threadIdx.x;
    float4 v = ((const float4*)x)[i];
    uint2 o;
    o.x = pack2(v.x, v.y);
    o.y = pack2(v.z, v.w);
    ((uint2*)g_Xr)[i] = o;
}

// ---------------------------------------------------------------------------
// Prepass B: transpose + fp16: g_Wr[w][n][k] = W[k][n].
// ---------------------------------------------------------------------------
__global__ __launch_bounds__(256) void prepass_w(const float* __restrict__ wq,
                                                 const float* __restrict__ wk,
                                                 const float* __restrict__ wv,
                                                 const float* __restrict__ wo) {
    __shared__ float t[32][33];
    const int w = blockIdx.z;
    const float* W = (w == 0) ? wq : (w == 1) ? wk : (w == 2) ? wv : wo;
    __half* D = g_Wr[w];
    const int k0 = blockIdx.y * 32, n0 = blockIdx.x * 32;
    const int tx = threadIdx.x & 31, ty = threadIdx.x >> 5;
#pragma unroll
    for (int j = 0; j < 4; j++)
        t[ty + 8 * j][tx] = W[(k0 + ty + 8 * j) * DM + n0 + tx];
    __syncthreads();
#pragma unroll
    for (int j = 0; j < 4; j++)
        D[(n0 + ty + 8 * j) * DM + k0 + tx] = __float2half_rn(t[tx][ty + 8 * j]);
}

// ---------------------------------------------------------------------------
// fp16 tensor-core GEMM: C[4096,1024] = A @ Wr^T (Wr is [n][k] fp16).
// Tile 128x128, BK=32 halves, cp.async double-buffered. 8 warps (2m x 4n),
// warp tile 64x32, m16n8k16. Static smem ~40 KB.
// MODE 0: A=g_O, B=g_Wr[3], C=Cp fp32 row-major.
// MODE 1: A=g_Xr, B=g_Wr[z], C=g_Q/g_K/g_V fp16 head layout (Q scaled 0.125).
// ---------------------------------------------------------------------------
#define GSTR 40   // halves per row (32+8): 80B stride = 5x16B (cp.async-OK),
                  // word banks (20g+t)%32 all distinct -> conflict-free

template <int MODE>
__global__ __launch_bounds__(256) void gemm_h(float* __restrict__ Cp) {
    __shared__ __align__(16) __half As[2][128 * GSTR];
    __shared__ __align__(16) __half Bs[2][128 * GSTR];

    const int tid = threadIdx.x;
    const int lane = tid & 31, wid = tid >> 5;
    const int g = lane >> 2, t = lane & 3;
    const int wm = wid & 1, wn = wid >> 1;
    const int row0 = blockIdx.y * 128;
    const int col0 = blockIdx.x * 128;
    const int z = (MODE == 0) ? 3 : blockIdx.z;

    const __half* A = (MODE == 0) ? (const __half*)g_O : (const __half*)g_Xr;
    const __half* B = g_Wr[z];

    float acc[4][4][4] = {};

    // Loaders: 128 rows x 64B = 512 16B-segs per matrix, 2/thread each.
#define LOADT(k0, buf)                                                        \
    do {                                                                      \
        _Pragma("unroll")                                                     \
        for (int j = 0; j < 2; j++) {                                         \
            const int s = tid + j * 256;                                      \
            const int r = s >> 2, c = (s & 3) * 8;                            \
            cp16(&As[buf][r * GSTR + c], &A[(row0 + r) * DM + (k0) + c]);     \
            cp16(&Bs[buf][r * GSTR + c], &B[(col0 + r) * DM + (k0) + c]);     \
        }                                                                     \
        cp_commit();                                                          \
    } while (0)

    LOADT(0, 0);

    for (int it = 0; it < DM / 32; it++) {
        const int buf = it & 1;
        if (it + 1 < DM / 32) {
            LOADT((it + 1) * 32, buf ^ 1);
            cp_wait<1>();
        } else {
            cp_wait<0>();
        }
        __syncthreads();

#pragma unroll
        for (int kt = 0; kt < 2; kt++) {
            const int kk = kt * 16;
            unsigned a[4][4], b[4][2];
#pragma unroll
            for (int mi = 0; mi < 4; mi++) {
                const __half* base = &As[buf][(wm * 64 + mi * 16) * GSTR + kk];
                a[mi][0] = *(const unsigned*)&base[g * GSTR + 2 * t];
                a[mi][1] = *(const unsigned*)&base[(g + 8) * GSTR + 2 * t];
                a[mi][2] = *(const unsigned*)&base[g * GSTR + 2 * t + 8];
                a[mi][3] = *(const unsigned*)&base[(g + 8) * GSTR + 2 * t + 8];
            }
#pragma unroll
            for (int ni = 0; ni < 4; ni++) {
                const __half* base = &Bs[buf][(wn * 32 + ni * 8 + g) * GSTR + kk];
                b[ni][0] = *(const unsigned*)&base[2 * t];
                b[ni][1] = *(const unsigned*)&base[2 * t + 8];
            }
#pragma unroll
            for (int mi = 0; mi < 4; mi++)
#pragma unroll
                for (int ni = 0; ni < 4; ni++)
                    mma_f16(acc[mi][ni][0], acc[mi][ni][1], acc[mi][ni][2], acc[mi][ni][3],
                            a[mi][0], a[mi][1], a[mi][2], a[mi][3],
                            b[ni][0], b[ni][1]);
        }
        __syncthreads();
    }
#undef LOADT

    if (MODE == 0) {
#pragma unroll
        for (int mi = 0; mi < 4; mi++) {
            const int r0 = row0 + wm * 64 + mi * 16 + g;
#pragma unroll
            for (int ni = 0; ni < 4; ni++) {
                const int c = col0 + wn * 32 + ni * 8 + 2 * t;
                *(float2*)&Cp[r0 * DM + c] = make_float2(acc[mi][ni][0], acc[mi][ni][1]);
                *(float2*)&Cp[(r0 + 8) * DM + c] = make_float2(acc[mi][ni][2], acc[mi][ni][3]);
            }
        }
    } else {
        __half* C = (z == 0) ? g_Q : (z == 1) ? g_K : g_V;
        const float sc = (z == 0) ? 0.125f : 1.0f;
#pragma unroll
        for (int mi = 0; mi < 4; mi++) {
            const int r0 = row0 + wm * 64 + mi * 16 + g;
#pragma unroll
            for (int ni = 0; ni < 4; ni++) {
                const int c = col0 + wn * 32 + ni * 8 + 2 * t;
                const int hh = c >> 6, d = c & 63;
                __half* dst = &C[hh * (S_LEN * HD) + r0 * HD + d];
                *(unsigned*)dst = pack2(acc[mi][ni][0] * sc, acc[mi][ni][1] * sc);
                *(unsigned*)(dst + 8 * HD) = pack2(acc[mi][ni][2] * sc, acc[mi][ni][3] * sc);
            }
        }
    }
}

// ---------------------------------------------------------------------------
// Warp-specialized flash attention, fp16 mma, causal. Br=64, Bc=32.
// Consumers: warps 0-3 (warp w -> rows [16w,16w+16)), producers: warps 4-7
// (cp.async double-buffered K/V). P kept in registers (C-frag -> A-frag);
// V fragments via ldmatrix.x4.trans. Static smem ~18.4 KB.
// ---------------------------------------------------------------------------
#define KVS 72   // halves per row: 144B stride = 9x16B (cp.async-OK)

__global__ __launch_bounds__(256) void attn_h() {
    __shared__ __align__(16) __half Ks[2][32 * KVS];
    __shared__ __align__(16) __half Vs[2][32 * KVS];

    const int qb = (int)gridDim.x - 1 - (int)blockIdx.x;  // long CTAs first
    const int h  = blockIdx.y;
    const int tid = threadIdx.x;
    const int lane = tid & 31, wid = tid >> 5;
    const int g = lane >> 2, t = lane & 3;
    const bool producer = (wid >= 4);
    const int wm = wid & 3;

    const __half* Qh = g_Q + h * (S_LEN * HD);
    const __half* Kh = g_K + h * (S_LEN * HD);
    const __half* Vh = g_V + h * (S_LEN * HD);

    const int kb_end = 2 * qb + 1;

#define LOAD_KV(kb, buf)                                                      \
    do {                                                                      \
        const int t2 = tid - 128;                                             \
        _Pragma("unroll")                                                     \
        for (int j = 0; j < 2; j++) {                                         \
            const int s = t2 + j * 128;                                       \
            const int r = s >> 3, c = (s & 7) * 8;                            \
            cp16(&Ks[buf][r * KVS + c], &Kh[((kb) * 32 + r) * HD + c]);       \
            cp16(&Vs[buf][r * KVS + c], &Vh[((kb) * 32 + r) * HD + c]);       \
        }                                                                     \
        cp_commit();                                                          \
    } while (0)

    if (producer) LOAD_KV(0, 0);

    // Consumers: Q fragments in registers (4 k16 blocks).
    unsigned qf[4][4];
    // ldmatrix.trans lane offsets for V (row within 16-block, col 8-offset)
    const int vrow = (lane & 7) + ((lane >> 3) & 1) * 8;
    const int vcol = (lane >> 4) * 8;
    if (!producer) {
        const int q0 = qb * 64 + wm * 16 + g;
#pragma unroll
        for (int kt = 0; kt < 4; kt++) {
            const int kk = kt * 16;
            qf[kt][0] = *(const unsigned*)&Qh[q0 * HD + kk + 2 * t];
            qf[kt][1] = *(const unsigned*)&Qh[(q0 + 8) * HD + kk + 2 * t];
            qf[kt][2] = *(const unsigned*)&Qh[q0 * HD + kk + 2 * t + 8];
            qf[kt][3] = *(const unsigned*)&Qh[(q0 + 8) * HD + kk + 2 * t + 8];
        }
    }

    float m0 = NEG_INF, m1 = NEG_INF;
    float l0 = 0.0f, l1 = 0.0f;
    float o[8][4] = {};

    for (int kb = 0; kb <= kb_end; kb++) {
        const int buf = kb & 1;
        if (producer) {
            if (kb < kb_end) {
                LOAD_KV(kb + 1, buf ^ 1);
                cp_wait<1>();
            } else {
                cp_wait<0>();
            }
        }
        __syncthreads();    // tiles[buf] ready; prior reads of buf done

        if (!producer) {
            // ---- S = Q K^T ----
            float s[4][4] = {};
#pragma unroll
            for (int kt = 0; kt < 4; kt++) {
                const int kk = kt * 16;
#pragma unroll
                for (int ni = 0; ni < 4; ni++) {
                    const __half* bb = &Ks[buf][(ni * 8 + g) * KVS + kk];
                    mma_f16(s[ni][0], s[ni][1], s[ni][2], s[ni][3],
                            qf[kt][0], qf[kt][1], qf[kt][2], qf[kt][3],
                            *(const unsigned*)&bb[2 * t],
                            *(const unsigned*)&bb[2 * t + 8]);
                }
            }

            // ---- causal mask ----
            if (kb >= 2 * qb) {
                const int rg0 = qb * 64 + wm * 16 + g;
                const int rg1 = rg0 + 8;
#pragma unroll
                for (int ni = 0; ni < 4; ni++) {
                    const int cb = kb * 32 + ni * 8 + 2 * t;
                    if (cb > rg0) s[ni][0] = NEG_INF;
                    if (cb + 1 > rg0) s[ni][1] = NEG_INF;
                    if (cb > rg1) s[ni][2] = NEG_INF;
                    if (cb + 1 > rg1) s[ni][3] = NEG_INF;
                }
            }

            // ---- online softmax (warp-local) ----
            float pm0 = fmaxf(fmaxf(s[0][0], s[0][1]), fmaxf(s[1][0], s[1][1]));
            pm0 = fmaxf(pm0, fmaxf(fmaxf(s[2][0], s[2][1]), fmaxf(s[3][0], s[3][1])));
            float pm1 = fmaxf(fmaxf(s[0][2], s[0][3]), fmaxf(s[1][2], s[1][3]));
            pm1 = fmaxf(pm1, fmaxf(fmaxf(s[2][2], s[2][3]), fmaxf(s[3][2], s[3][3])));
#pragma unroll
            for (int off = 1; off < 4; off <<= 1) {
                pm0 = fmaxf(pm0, __shfl_xor_sync(0xffffffffu, pm0, off, 4));
                pm1 = fmaxf(pm1, __shfl_xor_sync(0xffffffffu, pm1, off, 4));
            }
            const float mx0 = fmaxf(m0, pm0);
            const float mx1 = fmaxf(m1, pm1);
            const float scl0 = __expf(m0 - mx0);
            const float scl1 = __expf(m1 - mx1);
            m0 = mx0; m1 = mx1;

            float p[4][4];
            float ps0 = 0.0f, ps1 = 0.0f;
#pragma unroll
            for (int ni = 0; ni < 4; ni++) {
                p[ni][0] = __expf(s[ni][0] - mx0);
                p[ni][1] = __expf(s[ni][1] - mx0);
                p[ni][2] = __expf(s[ni][2] - mx1);
                p[ni][3] = __expf(s[ni][3] - mx1);
                ps0 += p[ni][0] + p[ni][1];
                ps1 += p[ni][2] + p[ni][3];
            }
#pragma unroll
            for (int off = 1; off < 4; off <<= 1) {
                ps0 += __shfl_xor_sync(0xffffffffu, ps0, off, 4);
                ps1 += __shfl_xor_sync(0xffffffffu, ps1, off, 4);
            }
            l0 = l0 * scl0 + ps0;
            l1 = l1 * scl1 + ps1;

#pragma unroll
            for (int ni = 0; ni < 8; ni++) {
                o[ni][0] *= scl0; o[ni][1] *= scl0;
                o[ni][2] *= scl1; o[ni][3] *= scl1;
            }

            // ---- P (registers) @ V (ldmatrix.trans) ----
            unsigned pa[2][4];
#pragma unroll
            for (int jp = 0; jp < 2; jp++) {
                pa[jp][0] = pack2(p[2 * jp][0], p[2 * jp][1]);
                pa[jp][1] = pack2(p[2 * jp][2], p[2 * jp][3]);
                pa[jp][2] = pack2(p[2 * jp + 1][0], p[2 * jp + 1][1]);
                pa[jp][3] = pack2(p[2 * jp + 1][2], p[2 * jp + 1][3]);
            }
#pragma unroll
            for (int jp = 0; jp < 2; jp++) {
#pragma unroll
                for (int np = 0; np < 4; np++) {
                    unsigned v0, v1, v2, v3;
                    unsigned addr = (unsigned)__cvta_generic_to_shared(
                        &Vs[buf][(jp * 16 + vrow) * KVS + np * 16 + vcol]);
                    asm volatile(
                        "ldmatrix.sync.aligned.m8n8.x4.trans.shared.b16 "
                        "{%0,%1,%2,%3}, [%4];"
                        : "=r"(v0), "=r"(v1), "=r"(v2), "=r"(v3) : "r"(addr));
                    mma_f16(o[np * 2][0], o[np * 2][1], o[np * 2][2], o[np * 2][3],
                            pa[jp][0], pa[jp][1], pa[jp][2], pa[jp][3], v0, v1);
                    mma_f16(o[np * 2 + 1][0], o[np * 2 + 1][1],
                            o[np * 2 + 1][2], o[np * 2 + 1][3],
                            pa[jp][0], pa[jp][1], pa[jp][2], pa[jp][3], v2, v3);
                }
            }
        }
        __syncthreads();    // reads of tiles[buf] done
    }
#undef LOAD_KV

    if (!producer) {
        const float inv0 = 1.0f / l0;
        const float inv1 = 1.0f / l1;
        const int q0 = qb * 64 + wm * 16 + g;
#pragma unroll
        for (int ni = 0; ni < 8; ni++) {
            const int c = h * HD + ni * 8 + 2 * t;
            *(unsigned*)&g_O[q0 * DM + c] = pack2(o[ni][0] * inv0, o[ni][1] * inv0);
            *(unsigned*)&g_O[(q0 + 8) * DM + c] = pack2(o[ni][2] * inv1, o[ni][3] * inv1);
        }
    }
}

// ---------------------------------------------------------------------------
extern "C" void kernel_launch(void* const* d_in, const int* in_sizes, int n_in,
                              void* d_out, int out_size) {
    (void)in_sizes; (void)n_in; (void)out_size;
    const float* x  = (const float*)d_in[0];
    const float* Wq = (const float*)d_in[1];
    const float* Wk = (const float*)d_in[2];
    const float* Wv = (const float*)d_in[3];
    const float* Wo = (const float*)d_in[4];
    float* out = (float*)d_out;

    prepass_x<<<S_LEN * DM / 4 / 256, 256>>>(x);
    prepass_w<<<dim3(DM / 32, DM / 32, 4), 256>>>(Wq, Wk, Wv, Wo);

    gemm_h<1><<<dim3(DM / 128, S_LEN / 128, 3), 256>>>(nullptr);

    attn_h<<<dim3(S_LEN / 64, NH), 256>>>();

    gemm_h<0><<<dim3(DM / 128, S_LEN / 128, 1), 256>>>(out);
}

// round 9
// speedup vs baseline: 9.5717x; 1.0587x over previous
#include <cuda_runtime.h>
#include <cuda_fp16.h>
#include <cstdint>

#define S_LEN 4096
#define DM 1024
#define NH 16
#define HD 64
#define NEG_INF __int_as_float(0xff800000)

// Scratch (device globals: allocation-free per harness rules). All fp16.
__device__ __half g_Q[NH * S_LEN * HD];  // [h][s][d], pre-scaled 0.125
__device__ __half g_K[NH * S_LEN * HD];
__device__ __half g_V[NH * S_LEN * HD];
__device__ __half g_O[S_LEN * DM];       // [s][h*64+d]
__device__ __half g_Xr[S_LEN * DM];      // x in fp16
__device__ __half g_Wr[4][DM * DM];      // W^T: [n][k], k contiguous

__device__ __forceinline__ void mma_f16(float& d0, float& d1, float& d2, float& d3,
                                        unsigned a0, unsigned a1, unsigned a2, unsigned a3,
                                        unsigned b0, unsigned b1) {
    asm volatile(
        "mma.sync.aligned.m16n8k16.row.col.f32.f16.f16.f32 "
        "{%0,%1,%2,%3}, {%4,%5,%6,%7}, {%8,%9}, {%0,%1,%2,%3};"
        : "+f"(d0), "+f"(d1), "+f"(d2), "+f"(d3)
        : "r"(a0), "r"(a1), "r"(a2), "r"(a3), "r"(b0), "r"(b1));
}

__device__ __forceinline__ void cp16(void* smem_dst, const void* gsrc) {
    unsigned d = (unsigned)__cvta_generic_to_shared(smem_dst);
    asm volatile("cp.async.cg.shared.global [%0], [%1], 16;" :: "r"(d), "l"(gsrc));
}
__device__ __forceinline__ void cp_commit() { asm volatile("cp.async.commit_group;"); }
template <int N>
__device__ __forceinline__ void cp_wait() {
    asm volatile("cp.async.wait_group %0;" :: "n"(N));
}

__device__ __forceinline__ unsigned pack2(float a, float b) {
    __half2 h = __floats2half2_rn(a, b);
    return *(unsigned*)&h;
}

// ---------------------------------------------------------------------------
// Prepass A: x -> fp16.
// ---------------------------------------------------------------------------
__global__ __launch_bounds__(256) void prepass_x(const float* __restrict__ x) {
    int i = blockIdx.x * 256 + threadIdx.x;
    float4 v = ((const float4*)x)[i];
    uint2 o;
    o.x = pack2(v.x, v.y);
    o.y = pack2(v.z, v.w);
    ((uint2*)g_Xr)[i] = o;
}

// ---------------------------------------------------------------------------
// Prepass B: transpose + fp16: g_Wr[w][n][k] = W[k][n].
// ---------------------------------------------------------------------------
__global__ __launch_bounds__(256) void prepass_w(const float* __restrict__ wq,
                                                 const float* __restrict__ wk,
                                                 const float* __restrict__ wv,
                                                 const float* __restrict__ wo) {
    __shared__ float t[32][33];
    const int w = blockIdx.z;
    const float* W = (w == 0) ? wq : (w == 1) ? wk : (w == 2) ? wv : wo;
    __half* D = g_Wr[w];
    const int k0 = blockIdx.y * 32, n0 = blockIdx.x * 32;
    const int tx = threadIdx.x & 31, ty = threadIdx.x >> 5;
#pragma unroll
    for (int j = 0; j < 4; j++)
        t[ty + 8 * j][tx] = W[(k0 + ty + 8 * j) * DM + n0 + tx];
    __syncthreads();
#pragma unroll
    for (int j = 0; j < 4; j++)
        D[(n0 + ty + 8 * j) * DM + k0 + tx] = __float2half_rn(t[tx][ty + 8 * j]);
}

// ---------------------------------------------------------------------------
// fp16 tensor-core GEMM: C[4096,1024] = A @ Wr^T (Wr is [n][k] fp16).
// Tile 128x128, BK=32 halves, cp.async double-buffered. 8 warps (2m x 4n),
// warp tile 64x32, m16n8k16. Static smem ~40 KB.
// MODE 0: A=g_O, B=g_Wr[3], C=Cp fp32 row-major.
// MODE 1: A=g_Xr, B=g_Wr[z], C=g_Q/g_K/g_V fp16 head layout (Q scaled 0.125).
// ---------------------------------------------------------------------------
#define GSTR 40   // halves per row (32+8): 80B stride = 5x16B (cp.async-OK)

template <int MODE>
__global__ __launch_bounds__(256) void gemm_h(float* __restrict__ Cp) {
    __shared__ __align__(16) __half As[2][128 * GSTR];
    __shared__ __align__(16) __half Bs[2][128 * GSTR];

    const int tid = threadIdx.x;
    const int lane = tid & 31, wid = tid >> 5;
    const int g = lane >> 2, t = lane & 3;
    const int wm = wid & 1, wn = wid >> 1;
    const int row0 = blockIdx.y * 128;
    const int col0 = blockIdx.x * 128;
    const int z = (MODE == 0) ? 3 : blockIdx.z;

    const __half* A = (MODE == 0) ? (const __half*)g_O : (const __half*)g_Xr;
    const __half* B = g_Wr[z];

    float acc[4][4][4] = {};

#define LOADT(k0, buf)                                                        \
    do {                                                                      \
        _Pragma("unroll")                                                     \
        for (int j = 0; j < 2; j++) {                                         \
            const int s = tid + j * 256;                                      \
            const int r = s >> 2, c = (s & 3) * 8;                            \
            cp16(&As[buf][r * GSTR + c], &A[(row0 + r) * DM + (k0) + c]);     \
            cp16(&Bs[buf][r * GSTR + c], &B[(col0 + r) * DM + (k0) + c]);     \
        }                                                                     \
        cp_commit();                                                          \
    } while (0)

    LOADT(0, 0);

    for (int it = 0; it < DM / 32; it++) {
        const int buf = it & 1;
        if (it + 1 < DM / 32) {
            LOADT((it + 1) * 32, buf ^ 1);
            cp_wait<1>();
        } else {
            cp_wait<0>();
        }
        __syncthreads();

#pragma unroll
        for (int kt = 0; kt < 2; kt++) {
            const int kk = kt * 16;
            unsigned a[4][4], b[4][2];
#pragma unroll
            for (int mi = 0; mi < 4; mi++) {
                const __half* base = &As[buf][(wm * 64 + mi * 16) * GSTR + kk];
                a[mi][0] = *(const unsigned*)&base[g * GSTR + 2 * t];
                a[mi][1] = *(const unsigned*)&base[(g + 8) * GSTR + 2 * t];
                a[mi][2] = *(const unsigned*)&base[g * GSTR + 2 * t + 8];
                a[mi][3] = *(const unsigned*)&base[(g + 8) * GSTR + 2 * t + 8];
            }
#pragma unroll
            for (int ni = 0; ni < 4; ni++) {
                const __half* base = &Bs[buf][(wn * 32 + ni * 8 + g) * GSTR + kk];
                b[ni][0] = *(const unsigned*)&base[2 * t];
                b[ni][1] = *(const unsigned*)&base[2 * t + 8];
            }
#pragma unroll
            for (int mi = 0; mi < 4; mi++)
#pragma unroll
                for (int ni = 0; ni < 4; ni++)
                    mma_f16(acc[mi][ni][0], acc[mi][ni][1], acc[mi][ni][2], acc[mi][ni][3],
                            a[mi][0], a[mi][1], a[mi][2], a[mi][3],
                            b[ni][0], b[ni][1]);
        }
        __syncthreads();
    }
#undef LOADT

    if (MODE == 0) {
#pragma unroll
        for (int mi = 0; mi < 4; mi++) {
            const int r0 = row0 + wm * 64 + mi * 16 + g;
#pragma unroll
            for (int ni = 0; ni < 4; ni++) {
                const int c = col0 + wn * 32 + ni * 8 + 2 * t;
                *(float2*)&Cp[r0 * DM + c] = make_float2(acc[mi][ni][0], acc[mi][ni][1]);
                *(float2*)&Cp[(r0 + 8) * DM + c] = make_float2(acc[mi][ni][2], acc[mi][ni][3]);
            }
        }
    } else {
        __half* C = (z == 0) ? g_Q : (z == 1) ? g_K : g_V;
        const float sc = (z == 0) ? 0.125f : 1.0f;
#pragma unroll
        for (int mi = 0; mi < 4; mi++) {
            const int r0 = row0 + wm * 64 + mi * 16 + g;
#pragma unroll
            for (int ni = 0; ni < 4; ni++) {
                const int c = col0 + wn * 32 + ni * 8 + 2 * t;
                const int hh = c >> 6, d = c & 63;
                __half* dst = &C[hh * (S_LEN * HD) + r0 * HD + d];
                *(unsigned*)dst = pack2(acc[mi][ni][0] * sc, acc[mi][ni][1] * sc);
                *(unsigned*)(dst + 8 * HD) = pack2(acc[mi][ni][2] * sc, acc[mi][ni][3] * sc);
            }
        }
    }
}

// ---------------------------------------------------------------------------
// Flash attention, fp16 mma, causal. Br=128, Bc=32. All 8 warps compute
// (warp w -> rows [16w,16w+16)); all 256 threads issue next-tile cp.async
// (1 K-seg + 1 V-seg each) before the barrier — gemm_h-style double buffer.
// Row stats warp-local. P in registers; V via ldmatrix.x4.trans.
// Static smem ~18.4 KB. Grid (32, 16), long CTAs first.
// ---------------------------------------------------------------------------
#define KVS 72   // halves per row: 144B stride = 9x16B (cp.async-OK)

__global__ __launch_bounds__(256) void attn_h() {
    __shared__ __align__(16) __half Ks[2][32 * KVS];
    __shared__ __align__(16) __half Vs[2][32 * KVS];

    const int qb = (int)gridDim.x - 1 - (int)blockIdx.x;  // long CTAs first
    const int h  = blockIdx.y;
    const int tid = threadIdx.x;
    const int lane = tid & 31, wid = tid >> 5;
    const int g = lane >> 2, t = lane & 3;
    const int wm = wid;                   // 0..7 -> 16-row stripe

    const __half* Qh = g_Q + h * (S_LEN * HD);
    const __half* Kh = g_K + h * (S_LEN * HD);
    const __half* Vh = g_V + h * (S_LEN * HD);

    const int kb_end = 4 * qb + 3;        // inclusive; 128-row q block

    // All threads: 1 K-seg + 1 V-seg per tile (256 segs each).
#define LOAD_KV(kb, buf)                                                      \
    do {                                                                      \
        const int r = tid >> 3, c = (tid & 7) * 8;                            \
        cp16(&Ks[buf][r * KVS + c], &Kh[((kb) * 32 + r) * HD + c]);           \
        cp16(&Vs[buf][r * KVS + c], &Vh[((kb) * 32 + r) * HD + c]);           \
        cp_commit();                                                          \
    } while (0)

    LOAD_KV(0, 0);

    // Q fragments in registers (4 k16 blocks), rows qb*128 + wm*16 + {g, g+8}.
    unsigned qf[4][4];
    {
        const int q0 = qb * 128 + wm * 16 + g;
#pragma unroll
        for (int kt = 0; kt < 4; kt++) {
            const int kk = kt * 16;
            qf[kt][0] = *(const unsigned*)&Qh[q0 * HD + kk + 2 * t];
            qf[kt][1] = *(const unsigned*)&Qh[(q0 + 8) * HD + kk + 2 * t];
            qf[kt][2] = *(const unsigned*)&Qh[q0 * HD + kk + 2 * t + 8];
            qf[kt][3] = *(const unsigned*)&Qh[(q0 + 8) * HD + kk + 2 * t + 8];
        }
    }

    // ldmatrix.trans lane offsets for V
    const int vrow = (lane & 7) + ((lane >> 3) & 1) * 8;
    const int vcol = (lane >> 4) * 8;

    float m0 = NEG_INF, m1 = NEG_INF;
    float l0 = 0.0f, l1 = 0.0f;
    float o[8][4] = {};

    for (int kb = 0; kb <= kb_end; kb++) {
        const int buf = kb & 1;
        if (kb < kb_end) {
            LOAD_KV(kb + 1, buf ^ 1);
            cp_wait<1>();
        } else {
            cp_wait<0>();
        }
        __syncthreads();    // tiles[buf] ready; prior reads of buf done

        // ---- S = Q K^T ----
        float s[4][4] = {};
#pragma unroll
        for (int kt = 0; kt < 4; kt++) {
            const int kk = kt * 16;
#pragma unroll
            for (int ni = 0; ni < 4; ni++) {
                const __half* bb = &Ks[buf][(ni * 8 + g) * KVS + kk];
                mma_f16(s[ni][0], s[ni][1], s[ni][2], s[ni][3],
                        qf[kt][0], qf[kt][1], qf[kt][2], qf[kt][3],
                        *(const unsigned*)&bb[2 * t],
                        *(const unsigned*)&bb[2 * t + 8]);
            }
        }

        // ---- causal mask (diagonal 32-blocks of the 128-row q block) ----
        if (kb >= 4 * qb) {
            const int rg0 = qb * 128 + wm * 16 + g;
            const int rg1 = rg0 + 8;
#pragma unroll
            for (int ni = 0; ni < 4; ni++) {
                const int cb = kb * 32 + ni * 8 + 2 * t;
                if (cb > rg0) s[ni][0] = NEG_INF;
                if (cb + 1 > rg0) s[ni][1] = NEG_INF;
                if (cb > rg1) s[ni][2] = NEG_INF;
                if (cb + 1 > rg1) s[ni][3] = NEG_INF;
            }
        }

        // ---- online softmax (warp-local) ----
        float pm0 = fmaxf(fmaxf(s[0][0], s[0][1]), fmaxf(s[1][0], s[1][1]));
        pm0 = fmaxf(pm0, fmaxf(fmaxf(s[2][0], s[2][1]), fmaxf(s[3][0], s[3][1])));
        float pm1 = fmaxf(fmaxf(s[0][2], s[0][3]), fmaxf(s[1][2], s[1][3]));
        pm1 = fmaxf(pm1, fmaxf(fmaxf(s[2][2], s[2][3]), fmaxf(s[3][2], s[3][3])));
#pragma unroll
        for (int off = 1; off < 4; off <<= 1) {
            pm0 = fmaxf(pm0, __shfl_xor_sync(0xffffffffu, pm0, off, 4));
            pm1 = fmaxf(pm1, __shfl_xor_sync(0xffffffffu, pm1, off, 4));
        }
        const float mx0 = fmaxf(m0, pm0);
        const float mx1 = fmaxf(m1, pm1);
        const float scl0 = __expf(m0 - mx0);
        const float scl1 = __expf(m1 - mx1);
        m0 = mx0; m1 = mx1;

        float p[4][4];
        float ps0 = 0.0f, ps1 = 0.0f;
#pragma unroll
        for (int ni = 0; ni < 4; ni++) {
            p[ni][0] = __expf(s[ni][0] - mx0);
            p[ni][1] = __expf(s[ni][1] - mx0);
            p[ni][2] = __expf(s[ni][2] - mx1);
            p[ni][3] = __expf(s[ni][3] - mx1);
            ps0 += p[ni][0] + p[ni][1];
            ps1 += p[ni][2] + p[ni][3];
        }
#pragma unroll
        for (int off = 1; off < 4; off <<= 1) {
            ps0 += __shfl_xor_sync(0xffffffffu, ps0, off, 4);
            ps1 += __shfl_xor_sync(0xffffffffu, ps1, off, 4);
        }
        l0 = l0 * scl0 + ps0;
        l1 = l1 * scl1 + ps1;

#pragma unroll
        for (int ni = 0; ni < 8; ni++) {
            o[ni][0] *= scl0; o[ni][1] *= scl0;
            o[ni][2] *= scl1; o[ni][3] *= scl1;
        }

        // ---- P (registers) @ V (ldmatrix.trans) ----
        unsigned pa[2][4];
#pragma unroll
        for (int jp = 0; jp < 2; jp++) {
            pa[jp][0] = pack2(p[2 * jp][0], p[2 * jp][1]);
            pa[jp][1] = pack2(p[2 * jp][2], p[2 * jp][3]);
            pa[jp][2] = pack2(p[2 * jp + 1][0], p[2 * jp + 1][1]);
            pa[jp][3] = pack2(p[2 * jp + 1][2], p[2 * jp + 1][3]);
        }
#pragma unroll
        for (int jp = 0; jp < 2; jp++) {
#pragma unroll
            for (int np = 0; np < 4; np++) {
                unsigned v0, v1, v2, v3;
                unsigned addr = (unsigned)__cvta_generic_to_shared(
                    &Vs[buf][(jp * 16 + vrow) * KVS + np * 16 + vcol]);
                asm volatile(
                    "ldmatrix.sync.aligned.m8n8.x4.trans.shared.b16 "
                    "{%0,%1,%2,%3}, [%4];"
                    : "=r"(v0), "=r"(v1), "=r"(v2), "=r"(v3) : "r"(addr));
                mma_f16(o[np * 2][0], o[np * 2][1], o[np * 2][2], o[np * 2][3],
                        pa[jp][0], pa[jp][1], pa[jp][2], pa[jp][3], v0, v1);
                mma_f16(o[np * 2 + 1][0], o[np * 2 + 1][1],
                        o[np * 2 + 1][2], o[np * 2 + 1][3],
                        pa[jp][0], pa[jp][1], pa[jp][2], pa[jp][3], v2, v3);
            }
        }
        __syncthreads();    // reads of tiles[buf] done
    }
#undef LOAD_KV

    {
        const float inv0 = 1.0f / l0;
        const float inv1 = 1.0f / l1;
        const int q0 = qb * 128 + wm * 16 + g;
#pragma unroll
        for (int ni = 0; ni < 8; ni++) {
            const int c = h * HD + ni * 8 + 2 * t;
            *(unsigned*)&g_O[q0 * DM + c] = pack2(o[ni][0] * inv0, o[ni][1] * inv0);
            *(unsigned*)&g_O[(q0 + 8) * DM + c] = pack2(o[ni][2] * inv1, o[ni][3] * inv1);
        }
    }
}

// ---------------------------------------------------------------------------
extern "C" void kernel_launch(void* const* d_in, const int* in_sizes, int n_in,
                              void* d_out, int out_size) {
    (void)in_sizes; (void)n_in; (void)out_size;
    const float* x  = (const float*)d_in[0];
    const float* Wq = (const float*)d_in[1];
    const float* Wk = (const float*)d_in[2];
    const float* Wv = (const float*)d_in[3];
    const float* Wo = (const float*)d_in[4];
    float* out = (float*)d_out;

    prepass_x<<<S_LEN * DM / 4 / 256, 256>>>(x);
    prepass_w<<<dim3(DM / 32, DM / 32, 4), 256>>>(Wq, Wk, Wv, Wo);

    gemm_h<1><<<dim3(DM / 128, S_LEN / 128, 3), 256>>>(nullptr);

    attn_h<<<dim3(S_LEN / 128, NH), 256>>>();

    gemm_h<0><<<dim3(DM / 128, S_LEN / 128, 1), 256>>>(out);
}

// round 10
// speedup vs baseline: 10.2707x; 1.0730x over previous
#include <cuda_runtime.h>
#include <cuda_fp16.h>
#include <cstdint>

#define S_LEN 4096
#define DM 1024
#define NH 16
#define HD 64
#define NEG_INF __int_as_float(0xff800000)

// Scratch (device globals: allocation-free per harness rules). All fp16.
__device__ __half g_Q[NH * S_LEN * HD];  // [h][s][d], pre-scaled 0.125*log2(e)
__device__ __half g_K[NH * S_LEN * HD];
__device__ __half g_V[NH * S_LEN * HD];
__device__ __half g_O[S_LEN * DM];       // [s][h*64+d]
__device__ __half g_Xr[S_LEN * DM];      // x in fp16
__device__ __half g_Wr[4][DM * DM];      // W^T: [n][k], k contiguous

__device__ __forceinline__ void mma_f16(float& d0, float& d1, float& d2, float& d3,
                                        unsigned a0, unsigned a1, unsigned a2, unsigned a3,
                                        unsigned b0, unsigned b1) {
    asm volatile(
        "mma.sync.aligned.m16n8k16.row.col.f32.f16.f16.f32 "
        "{%0,%1,%2,%3}, {%4,%5,%6,%7}, {%8,%9}, {%0,%1,%2,%3};"
        : "+f"(d0), "+f"(d1), "+f"(d2), "+f"(d3)
        : "r"(a0), "r"(a1), "r"(a2), "r"(a3), "r"(b0), "r"(b1));
}

__device__ __forceinline__ void cp16(void* smem_dst, const void* gsrc) {
    unsigned d = (unsigned)__cvta_generic_to_shared(smem_dst);
    asm volatile("cp.async.cg.shared.global [%0], [%1], 16;" :: "r"(d), "l"(gsrc));
}
__device__ __forceinline__ void cp_commit() { asm volatile("cp.async.commit_group;"); }
template <int N>
__device__ __forceinline__ void cp_wait() {
    asm volatile("cp.async.wait_group %0;" :: "n"(N));
}

__device__ __forceinline__ unsigned pack2(float a, float b) {
    __half2 h = __floats2half2_rn(a, b);
    return *(unsigned*)&h;
}

// ---------------------------------------------------------------------------
// Prepass A: x -> fp16.
// ---------------------------------------------------------------------------
__global__ __launch_bounds__(256) void prepass_x(const float* __restrict__ x) {
    int i = blockIdx.x * 256 + threadIdx.x;
    float4 v = ((const float4*)x)[i];
    uint2 o;
    o.x = pack2(v.x, v.y);
    o.y = pack2(v.z, v.w);
    ((uint2*)g_Xr)[i] = o;
}

// ---------------------------------------------------------------------------
// Prepass B: transpose + fp16: g_Wr[w][n][k] = W[k][n].
// ---------------------------------------------------------------------------
__global__ __launch_bounds__(256) void prepass_w(const float* __restrict__ wq,
                                                 const float* __restrict__ wk,
                                                 const float* __restrict__ wv,
                                                 const float* __restrict__ wo) {
    __shared__ float t[32][33];
    const int w = blockIdx.z;
    const float* W = (w == 0) ? wq : (w == 1) ? wk : (w == 2) ? wv : wo;
    __half* D = g_Wr[w];
    const int k0 = blockIdx.y * 32, n0 = blockIdx.x * 32;
    const int tx = threadIdx.x & 31, ty = threadIdx.x >> 5;
#pragma unroll
    for (int j = 0; j < 4; j++)
        t[ty + 8 * j][tx] = W[(k0 + ty + 8 * j) * DM + n0 + tx];
    __syncthreads();
#pragma unroll
    for (int j = 0; j < 4; j++)
        D[(n0 + ty + 8 * j) * DM + k0 + tx] = __float2half_rn(t[tx][ty + 8 * j]);
}

// ---------------------------------------------------------------------------
// fp16 tensor-core GEMM: C[4096,1024] = A @ Wr^T (Wr is [n][k] fp16).
// Tile 128x128, BK=32 halves, cp.async double-buffered. 8 warps (2m x 4n),
// warp tile 64x32, m16n8k16. Static smem ~40 KB.
// MODE 0: A=g_O, B=g_Wr[3], C=Cp fp32 row-major.
// MODE 1: A=g_Xr, B=g_Wr[z], C=g_Q/g_K/g_V fp16 head layout
//         (Q scaled 0.125*log2e for exp2-domain softmax).
// ---------------------------------------------------------------------------
#define GSTR 40   // halves per row (32+8): 80B stride = 5x16B (cp.async-OK)

template <int MODE>
__global__ __launch_bounds__(256) void gemm_h(float* __restrict__ Cp) {
    __shared__ __align__(16) __half As[2][128 * GSTR];
    __shared__ __align__(16) __half Bs[2][128 * GSTR];

    const int tid = threadIdx.x;
    const int lane = tid & 31, wid = tid >> 5;
    const int g = lane >> 2, t = lane & 3;
    const int wm = wid & 1, wn = wid >> 1;
    const int row0 = blockIdx.y * 128;
    const int col0 = blockIdx.x * 128;
    const int z = (MODE == 0) ? 3 : blockIdx.z;

    const __half* A = (MODE == 0) ? (const __half*)g_O : (const __half*)g_Xr;
    const __half* B = g_Wr[z];

    float acc[4][4][4] = {};

#define LOADT(k0, buf)                                                        \
    do {                                                                      \
        _Pragma("unroll")                                                     \
        for (int j = 0; j < 2; j++) {                                         \
            const int s = tid + j * 256;                                      \
            const int r = s >> 2, c = (s & 3) * 8;                            \
            cp16(&As[buf][r * GSTR + c], &A[(row0 + r) * DM + (k0) + c]);     \
            cp16(&Bs[buf][r * GSTR + c], &B[(col0 + r) * DM + (k0) + c]);     \
        }                                                                     \
        cp_commit();                                                          \
    } while (0)

    LOADT(0, 0);

    for (int it = 0; it < DM / 32; it++) {
        const int buf = it & 1;
        if (it + 1 < DM / 32) {
            LOADT((it + 1) * 32, buf ^ 1);
            cp_wait<1>();
        } else {
            cp_wait<0>();
        }
        __syncthreads();

#pragma unroll
        for (int kt = 0; kt < 2; kt++) {
            const int kk = kt * 16;
            unsigned a[4][4], b[4][2];
#pragma unroll
            for (int mi = 0; mi < 4; mi++) {
                const __half* base = &As[buf][(wm * 64 + mi * 16) * GSTR + kk];
                a[mi][0] = *(const unsigned*)&base[g * GSTR + 2 * t];
                a[mi][1] = *(const unsigned*)&base[(g + 8) * GSTR + 2 * t];
                a[mi][2] = *(const unsigned*)&base[g * GSTR + 2 * t + 8];
                a[mi][3] = *(const unsigned*)&base[(g + 8) * GSTR + 2 * t + 8];
            }
#pragma unroll
            for (int ni = 0; ni < 4; ni++) {
                const __half* base = &Bs[buf][(wn * 32 + ni * 8 + g) * GSTR + kk];
                b[ni][0] = *(const unsigned*)&base[2 * t];
                b[ni][1] = *(const unsigned*)&base[2 * t + 8];
            }
#pragma unroll
            for (int mi = 0; mi < 4; mi++)
#pragma unroll
                for (int ni = 0; ni < 4; ni++)
                    mma_f16(acc[mi][ni][0], acc[mi][ni][1], acc[mi][ni][2], acc[mi][ni][3],
                            a[mi][0], a[mi][1], a[mi][2], a[mi][3],
                            b[ni][0], b[ni][1]);
        }
        __syncthreads();
    }
#undef LOADT

    if (MODE == 0) {
#pragma unroll
        for (int mi = 0; mi < 4; mi++) {
            const int r0 = row0 + wm * 64 + mi * 16 + g;
#pragma unroll
            for (int ni = 0; ni < 4; ni++) {
                const int c = col0 + wn * 32 + ni * 8 + 2 * t;
                *(float2*)&Cp[r0 * DM + c] = make_float2(acc[mi][ni][0], acc[mi][ni][1]);
                *(float2*)&Cp[(r0 + 8) * DM + c] = make_float2(acc[mi][ni][2], acc[mi][ni][3]);
            }
        }
    } else {
        __half* C = (z == 0) ? g_Q : (z == 1) ? g_K : g_V;
        // Q: fold 1/sqrt(64) and log2(e) so softmax runs in exp2 domain.
        const float sc = (z == 0) ? 0.125f * 1.4426950408889634f : 1.0f;
#pragma unroll
        for (int mi = 0; mi < 4; mi++) {
            const int r0 = row0 + wm * 64 + mi * 16 + g;
#pragma unroll
            for (int ni = 0; ni < 4; ni++) {
                const int c = col0 + wn * 32 + ni * 8 + 2 * t;
                const int hh = c >> 6, d = c & 63;
                __half* dst = &C[hh * (S_LEN * HD) + r0 * HD + d];
                *(unsigned*)dst = pack2(acc[mi][ni][0] * sc, acc[mi][ni][1] * sc);
                *(unsigned*)(dst + 8 * HD) = pack2(acc[mi][ni][2] * sc, acc[mi][ni][3] * sc);
            }
        }
    }
}

// ---------------------------------------------------------------------------
// Flash attention, fp16 mma, causal. Br=128, Bc=64. All 8 warps compute
// (warp w -> rows [16w,16w+16)); all 256 threads issue next-tile cp.async
// (2 K-segs + 2 V-segs each). Softmax in exp2 domain (Q pre-scaled by
// log2e/8). P overwrites S in registers. Static smem ~36.9 KB.
// ---------------------------------------------------------------------------
#define KVS 72   // halves per row: 144B stride = 9x16B (cp.async-OK)

__global__ __launch_bounds__(256) void attn_h() {
    __shared__ __align__(16) __half Ks[2][64 * KVS];
    __shared__ __align__(16) __half Vs[2][64 * KVS];

    const int qb = (int)gridDim.x - 1 - (int)blockIdx.x;  // long CTAs first
    const int h  = blockIdx.y;
    const int tid = threadIdx.x;
    const int lane = tid & 31, wid = tid >> 5;
    const int g = lane >> 2, t = lane & 3;
    const int wm = wid;                   // 0..7 -> 16-row stripe

    const __half* Qh = g_Q + h * (S_LEN * HD);
    const __half* Kh = g_K + h * (S_LEN * HD);
    const __half* Vh = g_V + h * (S_LEN * HD);

    const int kb_end = 2 * qb + 1;        // inclusive; 64-col kv blocks

    // 64 rows x 64 halves = 512 16B-segs per matrix; 2 K + 2 V per thread.
#define LOAD_KV(kb, buf)                                                      \
    do {                                                                      \
        _Pragma("unroll")                                                     \
        for (int j = 0; j < 2; j++) {                                         \
            const int s = tid + j * 256;                                      \
            const int r = s >> 3, c = (s & 7) * 8;                            \
            cp16(&Ks[buf][r * KVS + c], &Kh[((kb) * 64 + r) * HD + c]);       \
            cp16(&Vs[buf][r * KVS + c], &Vh[((kb) * 64 + r) * HD + c]);       \
        }                                                                     \
        cp_commit();                                                          \
    } while (0)

    LOAD_KV(0, 0);

    // Q fragments in registers (4 k16 blocks), rows qb*128 + wm*16 + {g, g+8}.
    unsigned qf[4][4];
    {
        const int q0 = qb * 128 + wm * 16 + g;
#pragma unroll
        for (int kt = 0; kt < 4; kt++) {
            const int kk = kt * 16;
            qf[kt][0] = *(const unsigned*)&Qh[q0 * HD + kk + 2 * t];
            qf[kt][1] = *(const unsigned*)&Qh[(q0 + 8) * HD + kk + 2 * t];
            qf[kt][2] = *(const unsigned*)&Qh[q0 * HD + kk + 2 * t + 8];
            qf[kt][3] = *(const unsigned*)&Qh[(q0 + 8) * HD + kk + 2 * t + 8];
        }
    }

    // ldmatrix.trans lane offsets for V
    const int vrow = (lane & 7) + ((lane >> 3) & 1) * 8;
    const int vcol = (lane >> 4) * 8;

    float m0 = NEG_INF, m1 = NEG_INF;
    float l0 = 0.0f, l1 = 0.0f;
    float o[8][4] = {};

    for (int kb = 0; kb <= kb_end; kb++) {
        const int buf = kb & 1;
        if (kb < kb_end) {
            LOAD_KV(kb + 1, buf ^ 1);
            cp_wait<1>();
        } else {
            cp_wait<0>();
        }
        __syncthreads();    // tiles[buf] ready; prior reads of buf done

        // ---- S = Q K^T : 16 rows x 64 cols per warp ----
        float s[8][4] = {};
#pragma unroll
        for (int kt = 0; kt < 4; kt++) {
            const int kk = kt * 16;
#pragma unroll
            for (int ni = 0; ni < 8; ni++) {
                const __half* bb = &Ks[buf][(ni * 8 + g) * KVS + kk];
                mma_f16(s[ni][0], s[ni][1], s[ni][2], s[ni][3],
                        qf[kt][0], qf[kt][1], qf[kt][2], qf[kt][3],
                        *(const unsigned*)&bb[2 * t],
                        *(const unsigned*)&bb[2 * t + 8]);
            }
        }

        // ---- causal mask (diagonal 64-blocks) ----
        if (kb >= 2 * qb) {
            const int rg0 = qb * 128 + wm * 16 + g;
            const int rg1 = rg0 + 8;
#pragma unroll
            for (int ni = 0; ni < 8; ni++) {
                const int cb = kb * 64 + ni * 8 + 2 * t;
                if (cb > rg0) s[ni][0] = NEG_INF;
                if (cb + 1 > rg0) s[ni][1] = NEG_INF;
                if (cb > rg1) s[ni][2] = NEG_INF;
                if (cb + 1 > rg1) s[ni][3] = NEG_INF;
            }
        }

        // ---- online softmax (warp-local, exp2 domain) ----
        float pm0 = fmaxf(s[0][0], s[0][1]);
        float pm1 = fmaxf(s[0][2], s[0][3]);
#pragma unroll
        for (int ni = 1; ni < 8; ni++) {
            pm0 = fmaxf(pm0, fmaxf(s[ni][0], s[ni][1]));
            pm1 = fmaxf(pm1, fmaxf(s[ni][2], s[ni][3]));
        }
#pragma unroll
        for (int off = 1; off < 4; off <<= 1) {
            pm0 = fmaxf(pm0, __shfl_xor_sync(0xffffffffu, pm0, off, 4));
            pm1 = fmaxf(pm1, __shfl_xor_sync(0xffffffffu, pm1, off, 4));
        }
        const float mx0 = fmaxf(m0, pm0);
        const float mx1 = fmaxf(m1, pm1);
        const float scl0 = exp2f(m0 - mx0);
        const float scl1 = exp2f(m1 - mx1);
        m0 = mx0; m1 = mx1;

        float ps0 = 0.0f, ps1 = 0.0f;
#pragma unroll
        for (int ni = 0; ni < 8; ni++) {         // P overwrites S in place
            s[ni][0] = exp2f(s[ni][0] - mx0);
            s[ni][1] = exp2f(s[ni][1] - mx0);
            s[ni][2] = exp2f(s[ni][2] - mx1);
            s[ni][3] = exp2f(s[ni][3] - mx1);
            ps0 += s[ni][0] + s[ni][1];
            ps1 += s[ni][2] + s[ni][3];
        }
#pragma unroll
        for (int off = 1; off < 4; off <<= 1) {
            ps0 += __shfl_xor_sync(0xffffffffu, ps0, off, 4);
            ps1 += __shfl_xor_sync(0xffffffffu, ps1, off, 4);
        }
        l0 = l0 * scl0 + ps0;
        l1 = l1 * scl1 + ps1;

#pragma unroll
        for (int ni = 0; ni < 8; ni++) {
            o[ni][0] *= scl0; o[ni][1] *= scl0;
            o[ni][2] *= scl1; o[ni][3] *= scl1;
        }

        // ---- P (registers) @ V (ldmatrix.trans) ----
#pragma unroll
        for (int jp = 0; jp < 4; jp++) {         // k16 blocks of the 64 kv rows
            unsigned pa0 = pack2(s[2 * jp][0], s[2 * jp][1]);
            unsigned pa1 = pack2(s[2 * jp][2], s[2 * jp][3]);
            unsigned pa2 = pack2(s[2 * jp + 1][0], s[2 * jp + 1][1]);
            unsigned pa3 = pack2(s[2 * jp + 1][2], s[2 * jp + 1][3]);
#pragma unroll
            for (int np = 0; np < 4; np++) {     // 16-col V groups
                unsigned v0, v1, v2, v3;
                unsigned addr = (unsigned)__cvta_generic_to_shared(
                    &Vs[buf][(jp * 16 + vrow) * KVS + np * 16 + vcol]);
                asm volatile(
                    "ldmatrix.sync.aligned.m8n8.x4.trans.shared.b16 "
                    "{%0,%1,%2,%3}, [%4];"
                    : "=r"(v0), "=r"(v1), "=r"(v2), "=r"(v3) : "r"(addr));
                mma_f16(o[np * 2][0], o[np * 2][1], o[np * 2][2], o[np * 2][3],
                        pa0, pa1, pa2, pa3, v0, v1);
                mma_f16(o[np * 2 + 1][0], o[np * 2 + 1][1],
                        o[np * 2 + 1][2], o[np * 2 + 1][3],
                        pa0, pa1, pa2, pa3, v2, v3);
            }
        }
        __syncthreads();    // reads of tiles[buf] done
    }
#undef LOAD_KV

    {
        const float inv0 = 1.0f / l0;
        const float inv1 = 1.0f / l1;
        const int q0 = qb * 128 + wm * 16 + g;
#pragma unroll
        for (int ni = 0; ni < 8; ni++) {
            const int c = h * HD + ni * 8 + 2 * t;
            *(unsigned*)&g_O[q0 * DM + c] = pack2(o[ni][0] * inv0, o[ni][1] * inv0);
            *(unsigned*)&g_O[(q0 + 8) * DM + c] = pack2(o[ni][2] * inv1, o[ni][3] * inv1);
        }
    }
}

// ---------------------------------------------------------------------------
extern "C" void kernel_launch(void* const* d_in, const int* in_sizes, int n_in,
                              void* d_out, int out_size) {
    (void)in_sizes; (void)n_in; (void)out_size;
    const float* x  = (const float*)d_in[0];
    const float* Wq = (const float*)d_in[1];
    const float* Wk = (const float*)d_in[2];
    const float* Wv = (const float*)d_in[3];
    const float* Wo = (const float*)d_in[4];
    float* out = (float*)d_out;

    prepass_x<<<S_LEN * DM / 4 / 256, 256>>>(x);
    prepass_w<<<dim3(DM / 32, DM / 32, 4), 256>>>(Wq, Wk, Wv, Wo);

    gemm_h<1><<<dim3(DM / 128, S_LEN / 128, 3), 256>>>(nullptr);

    attn_h<<<dim3(S_LEN / 128, NH), 256>>>();

    gemm_h<0><<<dim3(DM / 128, S_LEN / 128, 1), 256>>>(out);
}

// round 11
// speedup vs baseline: 10.6298x; 1.0350x over previous
#include <cuda_runtime.h>
#include <cuda_fp16.h>
#include <cstdint>

#define S_LEN 4096
#define DM 1024
#define NH 16
#define HD 64
#define NEG_INF __int_as_float(0xff800000)
#define ONES2 0x3C003C00u   // half2 {1.0, 1.0}

// Scratch (device globals: allocation-free per harness rules). All fp16.
__device__ __half g_Q[NH * S_LEN * HD];  // [h][s][d], pre-scaled 0.125*log2(e)
__device__ __half g_K[NH * S_LEN * HD];
__device__ __half g_V[NH * S_LEN * HD];
__device__ __half g_O[S_LEN * DM];       // [s][h*64+d]
__device__ __half g_Xr[S_LEN * DM];      // x in fp16
__device__ __half g_Wr[4][DM * DM];      // W^T: [n][k], k contiguous

__device__ __forceinline__ void mma_f16(float& d0, float& d1, float& d2, float& d3,
                                        unsigned a0, unsigned a1, unsigned a2, unsigned a3,
                                        unsigned b0, unsigned b1) {
    asm volatile(
        "mma.sync.aligned.m16n8k16.row.col.f32.f16.f16.f32 "
        "{%0,%1,%2,%3}, {%4,%5,%6,%7}, {%8,%9}, {%0,%1,%2,%3};"
        : "+f"(d0), "+f"(d1), "+f"(d2), "+f"(d3)
        : "r"(a0), "r"(a1), "r"(a2), "r"(a3), "r"(b0), "r"(b1));
}

__device__ __forceinline__ void cp16(void* smem_dst, const void* gsrc) {
    unsigned d = (unsigned)__cvta_generic_to_shared(smem_dst);
    asm volatile("cp.async.cg.shared.global [%0], [%1], 16;" :: "r"(d), "l"(gsrc));
}
__device__ __forceinline__ void cp_commit() { asm volatile("cp.async.commit_group;"); }
template <int N>
__device__ __forceinline__ void cp_wait() {
    asm volatile("cp.async.wait_group %0;" :: "n"(N));
}

__device__ __forceinline__ unsigned pack2(float a, float b) {
    __half2 h = __floats2half2_rn(a, b);
    return *(unsigned*)&h;
}

// ---------------------------------------------------------------------------
// Prepass A: x -> fp16.
// ---------------------------------------------------------------------------
__global__ __launch_bounds__(256) void prepass_x(const float* __restrict__ x) {
    int i = blockIdx.x * 256 + threadIdx.x;
    float4 v = ((const float4*)x)[i];
    uint2 o;
    o.x = pack2(v.x, v.y);
    o.y = pack2(v.z, v.w);
    ((uint2*)g_Xr)[i] = o;
}

// ---------------------------------------------------------------------------
// Prepass B: transpose + fp16: g_Wr[w][n][k] = W[k][n].
// ---------------------------------------------------------------------------
__global__ __launch_bounds__(256) void prepass_w(const float* __restrict__ wq,
                                                 const float* __restrict__ wk,
                                                 const float* __restrict__ wv,
                                                 const float* __restrict__ wo) {
    __shared__ float t[32][33];
    const int w = blockIdx.z;
    const float* W = (w == 0) ? wq : (w == 1) ? wk : (w == 2) ? wv : wo;
    __half* D = g_Wr[w];
    const int k0 = blockIdx.y * 32, n0 = blockIdx.x * 32;
    const int tx = threadIdx.x & 31, ty = threadIdx.x >> 5;
#pragma unroll
    for (int j = 0; j < 4; j++)
        t[ty + 8 * j][tx] = W[(k0 + ty + 8 * j) * DM + n0 + tx];
    __syncthreads();
#pragma unroll
    for (int j = 0; j < 4; j++)
        D[(n0 + ty + 8 * j) * DM + k0 + tx] = __float2half_rn(t[tx][ty + 8 * j]);
}

// ---------------------------------------------------------------------------
// fp16 tensor-core GEMM: C[4096,1024] = A @ Wr^T (Wr is [n][k] fp16).
// Tile 128x128, BK=32 halves, cp.async double-buffered with a SINGLE barrier
// per iteration (wait own group -> barrier -> issue next -> compute).
// 8 warps (2m x 4n), warp tile 64x32, m16n8k16. Static smem ~40 KB.
// ---------------------------------------------------------------------------
#define GSTR 40   // halves per row (32+8): 80B stride = 5x16B (cp.async-OK)

template <int MODE>
__global__ __launch_bounds__(256) void gemm_h(float* __restrict__ Cp) {
    __shared__ __align__(16) __half As[2][128 * GSTR];
    __shared__ __align__(16) __half Bs[2][128 * GSTR];

    const int tid = threadIdx.x;
    const int lane = tid & 31, wid = tid >> 5;
    const int g = lane >> 2, t = lane & 3;
    const int wm = wid & 1, wn = wid >> 1;
    const int row0 = blockIdx.y * 128;
    const int col0 = blockIdx.x * 128;
    const int z = (MODE == 0) ? 3 : blockIdx.z;

    const __half* A = (MODE == 0) ? (const __half*)g_O : (const __half*)g_Xr;
    const __half* B = g_Wr[z];

    float acc[4][4][4] = {};

#define LOADT(k0, buf)                                                        \
    do {                                                                      \
        _Pragma("unroll")                                                     \
        for (int j = 0; j < 2; j++) {                                         \
            const int s = tid + j * 256;                                      \
            const int r = s >> 2, c = (s & 3) * 8;                            \
            cp16(&As[buf][r * GSTR + c], &A[(row0 + r) * DM + (k0) + c]);     \
            cp16(&Bs[buf][r * GSTR + c], &B[(col0 + r) * DM + (k0) + c]);     \
        }                                                                     \
        cp_commit();                                                          \
    } while (0)

    LOADT(0, 0);

    for (int it = 0; it < DM / 32; it++) {
        const int buf = it & 1;
        cp_wait<0>();        // own copies of tile `it` done
        __syncthreads();     // all copies visible; prior-iter reads done
        if (it + 1 < DM / 32) LOADT((it + 1) * 32, buf ^ 1);

#pragma unroll
        for (int kt = 0; kt < 2; kt++) {
            const int kk = kt * 16;
            unsigned a[4][4], b[4][2];
#pragma unroll
            for (int mi = 0; mi < 4; mi++) {
                const __half* base = &As[buf][(wm * 64 + mi * 16) * GSTR + kk];
                a[mi][0] = *(const unsigned*)&base[g * GSTR + 2 * t];
                a[mi][1] = *(const unsigned*)&base[(g + 8) * GSTR + 2 * t];
                a[mi][2] = *(const unsigned*)&base[g * GSTR + 2 * t + 8];
                a[mi][3] = *(const unsigned*)&base[(g + 8) * GSTR + 2 * t + 8];
            }
#pragma unroll
            for (int ni = 0; ni < 4; ni++) {
                const __half* base = &Bs[buf][(wn * 32 + ni * 8 + g) * GSTR + kk];
                b[ni][0] = *(const unsigned*)&base[2 * t];
                b[ni][1] = *(const unsigned*)&base[2 * t + 8];
            }
#pragma unroll
            for (int mi = 0; mi < 4; mi++)
#pragma unroll
                for (int ni = 0; ni < 4; ni++)
                    mma_f16(acc[mi][ni][0], acc[mi][ni][1], acc[mi][ni][2], acc[mi][ni][3],
                            a[mi][0], a[mi][1], a[mi][2], a[mi][3],
                            b[ni][0], b[ni][1]);
        }
    }
#undef LOADT

    if (MODE == 0) {
#pragma unroll
        for (int mi = 0; mi < 4; mi++) {
            const int r0 = row0 + wm * 64 + mi * 16 + g;
#pragma unroll
            for (int ni = 0; ni < 4; ni++) {
                const int c = col0 + wn * 32 + ni * 8 + 2 * t;
                *(float2*)&Cp[r0 * DM + c] = make_float2(acc[mi][ni][0], acc[mi][ni][1]);
                *(float2*)&Cp[(r0 + 8) * DM + c] = make_float2(acc[mi][ni][2], acc[mi][ni][3]);
            }
        }
    } else {
        __half* C = (z == 0) ? g_Q : (z == 1) ? g_K : g_V;
        // Q: fold 1/sqrt(64) and log2(e) so softmax runs in exp2 domain.
        const float sc = (z == 0) ? 0.125f * 1.4426950408889634f : 1.0f;
#pragma unroll
        for (int mi = 0; mi < 4; mi++) {
            const int r0 = row0 + wm * 64 + mi * 16 + g;
#pragma unroll
            for (int ni = 0; ni < 4; ni++) {
                const int c = col0 + wn * 32 + ni * 8 + 2 * t;
                const int hh = c >> 6, d = c & 63;
                __half* dst = &C[hh * (S_LEN * HD) + r0 * HD + d];
                *(unsigned*)dst = pack2(acc[mi][ni][0] * sc, acc[mi][ni][1] * sc);
                *(unsigned*)(dst + 8 * HD) = pack2(acc[mi][ni][2] * sc, acc[mi][ni][3] * sc);
            }
        }
    }
}

// ---------------------------------------------------------------------------
// Flash attention, fp16 mma, causal. Br=128, Bc=64, 8 warps (16-row stripes).
// Single barrier per KV iteration. Softmax in exp2 domain with
// ex2.approx.f16x2 (packed P doubles as the PV A-fragment). Row sums via a
// ones-column MMA accumulated in fp32 (exactly consistent with P used in PV).
// Static smem ~36.9 KB.
// ---------------------------------------------------------------------------
#define KVS 72   // halves per row: 144B stride = 9x16B (cp.async-OK)

__global__ __launch_bounds__(256) void attn_h() {
    __shared__ __align__(16) __half Ks[2][64 * KVS];
    __shared__ __align__(16) __half Vs[2][64 * KVS];

    const int qb = (int)gridDim.x - 1 - (int)blockIdx.x;  // long CTAs first
    const int h  = blockIdx.y;
    const int tid = threadIdx.x;
    const int lane = tid & 31, wid = tid >> 5;
    const int g = lane >> 2, t = lane & 3;
    const int wm = wid;                   // 0..7 -> 16-row stripe

    const __half* Qh = g_Q + h * (S_LEN * HD);
    const __half* Kh = g_K + h * (S_LEN * HD);
    const __half* Vh = g_V + h * (S_LEN * HD);

    const int kb_end = 2 * qb + 1;        // inclusive; 64-col kv blocks

#define LOAD_KV(kb, buf)                                                      \
    do {                                                                      \
        _Pragma("unroll")                                                     \
        for (int j = 0; j < 2; j++) {                                         \
            const int s = tid + j * 256;                                      \
            const int r = s >> 3, c = (s & 7) * 8;                            \
            cp16(&Ks[buf][r * KVS + c], &Kh[((kb) * 64 + r) * HD + c]);       \
            cp16(&Vs[buf][r * KVS + c], &Vh[((kb) * 64 + r) * HD + c]);       \
        }                                                                     \
        cp_commit();                                                          \
    } while (0)

    LOAD_KV(0, 0);

    // Q fragments in registers (4 k16 blocks), rows qb*128 + wm*16 + {g, g+8}.
    unsigned qf[4][4];
    {
        const int q0 = qb * 128 + wm * 16 + g;
#pragma unroll
        for (int kt = 0; kt < 4; kt++) {
            const int kk = kt * 16;
            qf[kt][0] = *(const unsigned*)&Qh[q0 * HD + kk + 2 * t];
            qf[kt][1] = *(const unsigned*)&Qh[(q0 + 8) * HD + kk + 2 * t];
            qf[kt][2] = *(const unsigned*)&Qh[q0 * HD + kk + 2 * t + 8];
            qf[kt][3] = *(const unsigned*)&Qh[(q0 + 8) * HD + kk + 2 * t + 8];
        }
    }

    // ldmatrix.trans lane offsets for V
    const int vrow = (lane & 7) + ((lane >> 3) & 1) * 8;
    const int vcol = (lane >> 4) * 8;

    float m0 = NEG_INF, m1 = NEG_INF;
    float lac[4] = {};                    // row-sum accumulators (ones-MMA)
    float o[8][4] = {};

    for (int kb = 0; kb <= kb_end; kb++) {
        const int buf = kb & 1;
        cp_wait<0>();       // own copies of tile kb done
        __syncthreads();    // all copies visible; prior-iter reads done
        if (kb < kb_end) LOAD_KV(kb + 1, buf ^ 1);

        // ---- S = Q K^T : 16 rows x 64 cols per warp ----
        float s[8][4] = {};
#pragma unroll
        for (int kt = 0; kt < 4; kt++) {
            const int kk = kt * 16;
#pragma unroll
            for (int ni = 0; ni < 8; ni++) {
                const __half* bb = &Ks[buf][(ni * 8 + g) * KVS + kk];
                mma_f16(s[ni][0], s[ni][1], s[ni][2], s[ni][3],
                        qf[kt][0], qf[kt][1], qf[kt][2], qf[kt][3],
                        *(const unsigned*)&bb[2 * t],
                        *(const unsigned*)&bb[2 * t + 8]);
            }
        }

        // ---- causal mask (diagonal 64-blocks) ----
        if (kb >= 2 * qb) {
            const int rg0 = qb * 128 + wm * 16 + g;
            const int rg1 = rg0 + 8;
#pragma unroll
            for (int ni = 0; ni < 8; ni++) {
                const int cb = kb * 64 + ni * 8 + 2 * t;
                if (cb > rg0) s[ni][0] = NEG_INF;
                if (cb + 1 > rg0) s[ni][1] = NEG_INF;
                if (cb > rg1) s[ni][2] = NEG_INF;
                if (cb + 1 > rg1) s[ni][3] = NEG_INF;
            }
        }

        // ---- online max (warp-local, exp2 domain) ----
        float pm0 = fmaxf(s[0][0], s[0][1]);
        float pm1 = fmaxf(s[0][2], s[0][3]);
#pragma unroll
        for (int ni = 1; ni < 8; ni++) {
            pm0 = fmaxf(pm0, fmaxf(s[ni][0], s[ni][1]));
            pm1 = fmaxf(pm1, fmaxf(s[ni][2], s[ni][3]));
        }
#pragma unroll
        for (int off = 1; off < 4; off <<= 1) {
            pm0 = fmaxf(pm0, __shfl_xor_sync(0xffffffffu, pm0, off, 4));
            pm1 = fmaxf(pm1, __shfl_xor_sync(0xffffffffu, pm1, off, 4));
        }
        const float mx0 = fmaxf(m0, pm0);
        const float mx1 = fmaxf(m1, pm1);
        const float scl0 = exp2f(m0 - mx0);
        const float scl1 = exp2f(m1 - mx1);
        m0 = mx0; m1 = mx1;

        // ---- P = 2^(S-m) in fp16x2; packed regs ARE the PV A-fragments ----
        unsigned pp[8][2];
#pragma unroll
        for (int ni = 0; ni < 8; ni++) {
            unsigned e0 = pack2(s[ni][0] - mx0, s[ni][1] - mx0);
            unsigned e1 = pack2(s[ni][2] - mx1, s[ni][3] - mx1);
            asm("ex2.approx.f16x2 %0, %0;" : "+r"(e0));
            asm("ex2.approx.f16x2 %0, %0;" : "+r"(e1));
            pp[ni][0] = e0;
            pp[ni][1] = e1;
        }

        // ---- rescale accumulators ----
        lac[0] *= scl0; lac[1] *= scl0; lac[2] *= scl1; lac[3] *= scl1;
#pragma unroll
        for (int ni = 0; ni < 8; ni++) {
            o[ni][0] *= scl0; o[ni][1] *= scl0;
            o[ni][2] *= scl1; o[ni][3] *= scl1;
        }

        // ---- l += P @ 1 (ones-MMA, fp32 accum, consistent with PV's P) ----
#pragma unroll
        for (int jp = 0; jp < 4; jp++)
            mma_f16(lac[0], lac[1], lac[2], lac[3],
                    pp[2 * jp][0], pp[2 * jp][1],
                    pp[2 * jp + 1][0], pp[2 * jp + 1][1],
                    ONES2, ONES2);

        // ---- O += P V (ldmatrix.trans) ----
#pragma unroll
        for (int jp = 0; jp < 4; jp++) {
            const unsigned pa0 = pp[2 * jp][0], pa1 = pp[2 * jp][1];
            const unsigned pa2 = pp[2 * jp + 1][0], pa3 = pp[2 * jp + 1][1];
#pragma unroll
            for (int np = 0; np < 4; np++) {
                unsigned v0, v1, v2, v3;
                unsigned addr = (unsigned)__cvta_generic_to_shared(
                    &Vs[buf][(jp * 16 + vrow) * KVS + np * 16 + vcol]);
                asm volatile(
                    "ldmatrix.sync.aligned.m8n8.x4.trans.shared.b16 "
                    "{%0,%1,%2,%3}, [%4];"
                    : "=r"(v0), "=r"(v1), "=r"(v2), "=r"(v3) : "r"(addr));
                mma_f16(o[np * 2][0], o[np * 2][1], o[np * 2][2], o[np * 2][3],
                        pa0, pa1, pa2, pa3, v0, v1);
                mma_f16(o[np * 2 + 1][0], o[np * 2 + 1][1],
                        o[np * 2 + 1][2], o[np * 2 + 1][3],
                        pa0, pa1, pa2, pa3, v2, v3);
            }
        }
    }
#undef LOAD_KV

    {
        const float inv0 = 1.0f / lac[0];
        const float inv1 = 1.0f / lac[2];
        const int q0 = qb * 128 + wm * 16 + g;
#pragma unroll
        for (int ni = 0; ni < 8; ni++) {
            const int c = h * HD + ni * 8 + 2 * t;
            *(unsigned*)&g_O[q0 * DM + c] = pack2(o[ni][0] * inv0, o[ni][1] * inv0);
            *(unsigned*)&g_O[(q0 + 8) * DM + c] = pack2(o[ni][2] * inv1, o[ni][3] * inv1);
        }
    }
}

// ---------------------------------------------------------------------------
extern "C" void kernel_launch(void* const* d_in, const int* in_sizes, int n_in,
                              void* d_out, int out_size) {
    (void)in_sizes; (void)n_in; (void)out_size;
    const float* x  = (const float*)d_in[0];
    const float* Wq = (const float*)d_in[1];
    const float* Wk = (const float*)d_in[2];
    const float* Wv = (const float*)d_in[3];
    const float* Wo = (const float*)d_in[4];
    float* out = (float*)d_out;

    prepass_x<<<S_LEN * DM / 4 / 256, 256>>>(x);
    prepass_w<<<dim3(DM / 32, DM / 32, 4), 256>>>(Wq, Wk, Wv, Wo);

    gemm_h<1><<<dim3(DM / 128, S_LEN / 128, 3), 256>>>(nullptr);

    attn_h<<<dim3(S_LEN / 128, NH), 256>>>();

    gemm_h<0><<<dim3(DM / 128, S_LEN / 128, 1), 256>>>(out);
}

// round 12
// speedup vs baseline: 10.8115x; 1.0171x over previous
#include <cuda_runtime.h>
#include <cuda_fp16.h>
#include <cstdint>

#define S_LEN 4096
#define DM 1024
#define NH 16
#define HD 64
#define NEG_INF __int_as_float(0xff800000)
#define ONES2 0x3C003C00u   // half2 {1.0, 1.0}

// Scratch (device globals: allocation-free per harness rules). All fp16.
__device__ __half g_Q[NH * S_LEN * HD];  // [h][s][d], pre-scaled 0.125*log2(e)
__device__ __half g_K[NH * S_LEN * HD];
__device__ __half g_V[NH * S_LEN * HD];
__device__ __half g_O[S_LEN * DM];       // [s][h*64+d]
__device__ __half g_Xr[S_LEN * DM];      // x in fp16
__device__ __half g_Wr[4][DM * DM];      // W^T: [n][k], k contiguous

__device__ __forceinline__ void mma_f16(float& d0, float& d1, float& d2, float& d3,
                                        unsigned a0, unsigned a1, unsigned a2, unsigned a3,
                                        unsigned b0, unsigned b1) {
    asm volatile(
        "mma.sync.aligned.m16n8k16.row.col.f32.f16.f16.f32 "
        "{%0,%1,%2,%3}, {%4,%5,%6,%7}, {%8,%9}, {%0,%1,%2,%3};"
        : "+f"(d0), "+f"(d1), "+f"(d2), "+f"(d3)
        : "r"(a0), "r"(a1), "r"(a2), "r"(a3), "r"(b0), "r"(b1));
}

__device__ __forceinline__ void ldm_x4(unsigned& r0, unsigned& r1, unsigned& r2,
                                       unsigned& r3, unsigned addr) {
    asm volatile("ldmatrix.sync.aligned.m8n8.x4.shared.b16 {%0,%1,%2,%3}, [%4];"
                 : "=r"(r0), "=r"(r1), "=r"(r2), "=r"(r3) : "r"(addr));
}

__device__ __forceinline__ void cp16(void* smem_dst, const void* gsrc) {
    unsigned d = (unsigned)__cvta_generic_to_shared(smem_dst);
    asm volatile("cp.async.cg.shared.global [%0], [%1], 16;" :: "r"(d), "l"(gsrc));
}
__device__ __forceinline__ void cp_commit() { asm volatile("cp.async.commit_group;"); }
template <int N>
__device__ __forceinline__ void cp_wait() {
    asm volatile("cp.async.wait_group %0;" :: "n"(N));
}

__device__ __forceinline__ unsigned pack2(float a, float b) {
    __half2 h = __floats2half2_rn(a, b);
    return *(unsigned*)&h;
}

// ---------------------------------------------------------------------------
// Prepass A: x -> fp16.
// ---------------------------------------------------------------------------
__global__ __launch_bounds__(256) void prepass_x(const float* __restrict__ x) {
    int i = blockIdx.x * 256 + threadIdx.x;
    float4 v = ((const float4*)x)[i];
    uint2 o;
    o.x = pack2(v.x, v.y);
    o.y = pack2(v.z, v.w);
    ((uint2*)g_Xr)[i] = o;
}

// ---------------------------------------------------------------------------
// Prepass B: transpose + fp16: g_Wr[w][n][k] = W[k][n].
// ---------------------------------------------------------------------------
__global__ __launch_bounds__(256) void prepass_w(const float* __restrict__ wq,
                                                 const float* __restrict__ wk,
                                                 const float* __restrict__ wv,
                                                 const float* __restrict__ wo) {
    __shared__ float t[32][33];
    const int w = blockIdx.z;
    const float* W = (w == 0) ? wq : (w == 1) ? wk : (w == 2) ? wv : wo;
    __half* D = g_Wr[w];
    const int k0 = blockIdx.y * 32, n0 = blockIdx.x * 32;
    const int tx = threadIdx.x & 31, ty = threadIdx.x >> 5;
#pragma unroll
    for (int j = 0; j < 4; j++)
        t[ty + 8 * j][tx] = W[(k0 + ty + 8 * j) * DM + n0 + tx];
    __syncthreads();
#pragma unroll
    for (int j = 0; j < 4; j++)
        D[(n0 + ty + 8 * j) * DM + k0 + tx] = __float2half_rn(t[tx][ty + 8 * j]);
}

// ---------------------------------------------------------------------------
// fp16 tensor-core GEMM: C[4096,1024] = A @ Wr^T (Wr is [n][k] fp16).
// Tile 128x128, BK=32, cp.async double-buffered, SINGLE barrier/iter.
// Fragments via ldmatrix.x4 (A: 4, B: 2 per kt). Static smem ~40 KB.
// ---------------------------------------------------------------------------
#define GSTR 40   // halves per row (32+8): 80B stride = 5x16B (cp.async-OK)

template <int MODE>
__global__ __launch_bounds__(256) void gemm_h(float* __restrict__ Cp) {
    __shared__ __align__(16) __half As[2][128 * GSTR];
    __shared__ __align__(16) __half Bs[2][128 * GSTR];

    const int tid = threadIdx.x;
    const int lane = tid & 31, wid = tid >> 5;
    const int g = lane >> 2, t = lane & 3;
    const int wm = wid & 1, wn = wid >> 1;
    const int row0 = blockIdx.y * 128;
    const int col0 = blockIdx.x * 128;
    const int z = (MODE == 0) ? 3 : blockIdx.z;

    const __half* A = (MODE == 0) ? (const __half*)g_O : (const __half*)g_Xr;
    const __half* B = g_Wr[z];

    // ldmatrix lane roles
    const int lr = lane & 7, quad = lane >> 3;
    const int arow = lr + (quad & 1) * 8;        // A: r0=rows0-7,k0-7; r1=rows8-15
    const int acol = (quad >> 1) * 8;
    const int brow = lr + (quad >> 1) * 8;       // B: r0,r1 = n0-7 k0/8; r2,r3 = n8-15
    const int bcol = (quad & 1) * 8;

    unsigned asb[2], bsb[2];
#pragma unroll
    for (int b = 0; b < 2; b++) {
        asb[b] = (unsigned)__cvta_generic_to_shared(&As[b][0]);
        bsb[b] = (unsigned)__cvta_generic_to_shared(&Bs[b][0]);
    }

    float acc[4][4][4] = {};

#define LOADT(k0, buf)                                                        \
    do {                                                                      \
        _Pragma("unroll")                                                     \
        for (int j = 0; j < 2; j++) {                                         \
            const int s = tid + j * 256;                                      \
            const int r = s >> 2, c = (s & 3) * 8;                            \
            cp16(&As[buf][r * GSTR + c], &A[(row0 + r) * DM + (k0) + c]);     \
            cp16(&Bs[buf][r * GSTR + c], &B[(col0 + r) * DM + (k0) + c]);     \
        }                                                                     \
        cp_commit();                                                          \
    } while (0)

    LOADT(0, 0);

    for (int it = 0; it < DM / 32; it++) {
        const int buf = it & 1;
        cp_wait<0>();        // own copies of tile `it` done
        __syncthreads();     // all copies visible; prior-iter reads done
        if (it + 1 < DM / 32) LOADT((it + 1) * 32, buf ^ 1);

#pragma unroll
        for (int kt = 0; kt < 2; kt++) {
            const int kk = kt * 16;
            unsigned a[4][4], b[4][2];
#pragma unroll
            for (int mi = 0; mi < 4; mi++)
                ldm_x4(a[mi][0], a[mi][1], a[mi][2], a[mi][3],
                       asb[buf] + ((wm * 64 + mi * 16 + arow) * GSTR + kk + acol) * 2);
#pragma unroll
            for (int pr = 0; pr < 2; pr++)
                ldm_x4(b[2 * pr][0], b[2 * pr][1], b[2 * pr + 1][0], b[2 * pr + 1][1],
                       bsb[buf] + ((wn * 32 + pr * 16 + brow) * GSTR + kk + bcol) * 2);
#pragma unroll
            for (int mi = 0; mi < 4; mi++)
#pragma unroll
                for (int ni = 0; ni < 4; ni++)
                    mma_f16(acc[mi][ni][0], acc[mi][ni][1], acc[mi][ni][2], acc[mi][ni][3],
                            a[mi][0], a[mi][1], a[mi][2], a[mi][3],
                            b[ni][0], b[ni][1]);
        }
    }
#undef LOADT

    if (MODE == 0) {
#pragma unroll
        for (int mi = 0; mi < 4; mi++) {
            const int r0 = row0 + wm * 64 + mi * 16 + g;
#pragma unroll
            for (int ni = 0; ni < 4; ni++) {
                const int c = col0 + wn * 32 + ni * 8 + 2 * t;
                *(float2*)&Cp[r0 * DM + c] = make_float2(acc[mi][ni][0], acc[mi][ni][1]);
                *(float2*)&Cp[(r0 + 8) * DM + c] = make_float2(acc[mi][ni][2], acc[mi][ni][3]);
            }
        }
    } else {
        __half* C = (z == 0) ? g_Q : (z == 1) ? g_K : g_V;
        // Q: fold 1/sqrt(64) and log2(e) so softmax runs in exp2 domain.
        const float sc = (z == 0) ? 0.125f * 1.4426950408889634f : 1.0f;
#pragma unroll
        for (int mi = 0; mi < 4; mi++) {
            const int r0 = row0 + wm * 64 + mi * 16 + g;
#pragma unroll
            for (int ni = 0; ni < 4; ni++) {
                const int c = col0 + wn * 32 + ni * 8 + 2 * t;
                const int hh = c >> 6, d = c & 63;
                __half* dst = &C[hh * (S_LEN * HD) + r0 * HD + d];
                *(unsigned*)dst = pack2(acc[mi][ni][0] * sc, acc[mi][ni][1] * sc);
                *(unsigned*)(dst + 8 * HD) = pack2(acc[mi][ni][2] * sc, acc[mi][ni][3] * sc);
            }
        }
    }
}

// ---------------------------------------------------------------------------
// Flash attention, fp16 mma, causal. Br=128, Bc=64, 8 warps (16-row stripes).
// Single barrier per KV iteration. K fragments via ldmatrix.x4 (2 mmas per
// load); softmax exp2-domain ex2.approx.f16x2; row sums via ones-MMA.
// Static smem ~36.9 KB.
// ---------------------------------------------------------------------------
#define KVS 72   // halves per row: 144B stride = 9x16B (cp.async-OK)

__global__ __launch_bounds__(256) void attn_h() {
    __shared__ __align__(16) __half Ks[2][64 * KVS];
    __shared__ __align__(16) __half Vs[2][64 * KVS];

    const int qb = (int)gridDim.x - 1 - (int)blockIdx.x;  // long CTAs first
    const int h  = blockIdx.y;
    const int tid = threadIdx.x;
    const int lane = tid & 31, wid = tid >> 5;
    const int g = lane >> 2, t = lane & 3;
    const int wm = wid;                   // 0..7 -> 16-row stripe

    const __half* Qh = g_Q + h * (S_LEN * HD);
    const __half* Kh = g_K + h * (S_LEN * HD);
    const __half* Vh = g_V + h * (S_LEN * HD);

    const int kb_end = 2 * qb + 1;        // inclusive; 64-col kv blocks

#define LOAD_KV(kb, buf)                                                      \
    do {                                                                      \
        _Pragma("unroll")                                                     \
        for (int j = 0; j < 2; j++) {                                         \
            const int s = tid + j * 256;                                      \
            const int r = s >> 3, c = (s & 7) * 8;                            \
            cp16(&Ks[buf][r * KVS + c], &Kh[((kb) * 64 + r) * HD + c]);       \
            cp16(&Vs[buf][r * KVS + c], &Vh[((kb) * 64 + r) * HD + c]);       \
        }                                                                     \
        cp_commit();                                                          \
    } while (0)

    LOAD_KV(0, 0);

    // Q fragments in registers (4 k16 blocks), rows qb*128 + wm*16 + {g, g+8}.
    unsigned qf[4][4];
    {
        const int q0 = qb * 128 + wm * 16 + g;
#pragma unroll
        for (int kt = 0; kt < 4; kt++) {
            const int kk = kt * 16;
            qf[kt][0] = *(const unsigned*)&Qh[q0 * HD + kk + 2 * t];
            qf[kt][1] = *(const unsigned*)&Qh[(q0 + 8) * HD + kk + 2 * t];
            qf[kt][2] = *(const unsigned*)&Qh[q0 * HD + kk + 2 * t + 8];
            qf[kt][3] = *(const unsigned*)&Qh[(q0 + 8) * HD + kk + 2 * t + 8];
        }
    }

    // ldmatrix lane roles
    const int lr = lane & 7, quad = lane >> 3;
    const int krow = lr + (quad >> 1) * 8;   // K (non-trans): n-row within pair
    const int kcol = (quad & 1) * 8;
    const int vrow = lr + (quad & 1) * 8;    // V (trans)
    const int vcol = (quad >> 1) * 8;

    unsigned ksb[2], vsb[2];
#pragma unroll
    for (int b = 0; b < 2; b++) {
        ksb[b] = (unsigned)__cvta_generic_to_shared(&Ks[b][0]);
        vsb[b] = (unsigned)__cvta_generic_to_shared(&Vs[b][0]);
    }

    float m0 = NEG_INF, m1 = NEG_INF;
    float lac[4] = {};                    // row-sum accumulators (ones-MMA)
    float o[8][4] = {};

    for (int kb = 0; kb <= kb_end; kb++) {
        const int buf = kb & 1;
        cp_wait<0>();       // own copies of tile kb done
        __syncthreads();    // all copies visible; prior-iter reads done
        if (kb < kb_end) LOAD_KV(kb + 1, buf ^ 1);

        // ---- S = Q K^T : 16 rows x 64 cols per warp ----
        float s[8][4] = {};
#pragma unroll
        for (int kt = 0; kt < 4; kt++) {
            const int kk = kt * 16;
#pragma unroll
            for (int pr = 0; pr < 4; pr++) {       // n-block pairs
                unsigned b0e, b1e, b0o, b1o;
                ldm_x4(b0e, b1e, b0o, b1o,
                       ksb[buf] + ((pr * 16 + krow) * KVS + kk + kcol) * 2);
                mma_f16(s[2 * pr][0], s[2 * pr][1], s[2 * pr][2], s[2 * pr][3],
                        qf[kt][0], qf[kt][1], qf[kt][2], qf[kt][3], b0e, b1e);
                mma_f16(s[2 * pr + 1][0], s[2 * pr + 1][1],
                        s[2 * pr + 1][2], s[2 * pr + 1][3],
                        qf[kt][0], qf[kt][1], qf[kt][2], qf[kt][3], b0o, b1o);
            }
        }

        // ---- causal mask (diagonal 64-blocks) ----
        if (kb >= 2 * qb) {
            const int rg0 = qb * 128 + wm * 16 + g;
            const int rg1 = rg0 + 8;
#pragma unroll
            for (int ni = 0; ni < 8; ni++) {
                const int cb = kb * 64 + ni * 8 + 2 * t;
                if (cb > rg0) s[ni][0] = NEG_INF;
                if (cb + 1 > rg0) s[ni][1] = NEG_INF;
                if (cb > rg1) s[ni][2] = NEG_INF;
                if (cb + 1 > rg1) s[ni][3] = NEG_INF;
            }
        }

        // ---- online max: tree reduction then 4-lane shuffles ----
        float a0[4], a1[4];
#pragma unroll
        for (int j = 0; j < 4; j++) {
            a0[j] = fmaxf(fmaxf(s[2 * j][0], s[2 * j][1]),
                          fmaxf(s[2 * j + 1][0], s[2 * j + 1][1]));
            a1[j] = fmaxf(fmaxf(s[2 * j][2], s[2 * j][3]),
                          fmaxf(s[2 * j + 1][2], s[2 * j + 1][3]));
        }
        float pm0 = fmaxf(fmaxf(a0[0], a0[1]), fmaxf(a0[2], a0[3]));
        float pm1 = fmaxf(fmaxf(a1[0], a1[1]), fmaxf(a1[2], a1[3]));
#pragma unroll
        for (int off = 1; off < 4; off <<= 1) {
            pm0 = fmaxf(pm0, __shfl_xor_sync(0xffffffffu, pm0, off, 4));
            pm1 = fmaxf(pm1, __shfl_xor_sync(0xffffffffu, pm1, off, 4));
        }
        const float mx0 = fmaxf(m0, pm0);
        const float mx1 = fmaxf(m1, pm1);
        const float scl0 = exp2f(m0 - mx0);
        const float scl1 = exp2f(m1 - mx1);
        m0 = mx0; m1 = mx1;

        // ---- P = 2^(S-m) in fp16x2; packed regs ARE the PV A-fragments ----
        unsigned pp[8][2];
#pragma unroll
        for (int ni = 0; ni < 8; ni++) {
            unsigned e0 = pack2(s[ni][0] - mx0, s[ni][1] - mx0);
            unsigned e1 = pack2(s[ni][2] - mx1, s[ni][3] - mx1);
            asm("ex2.approx.f16x2 %0, %0;" : "+r"(e0));
            asm("ex2.approx.f16x2 %0, %0;" : "+r"(e1));
            pp[ni][0] = e0;
            pp[ni][1] = e1;
        }

        // ---- rescale accumulators ----
        lac[0] *= scl0; lac[1] *= scl0; lac[2] *= scl1; lac[3] *= scl1;
#pragma unroll
        for (int ni = 0; ni < 8; ni++) {
            o[ni][0] *= scl0; o[ni][1] *= scl0;
            o[ni][2] *= scl1; o[ni][3] *= scl1;
        }

        // ---- l += P @ 1 (ones-MMA, fp32 accum, consistent with PV's P) ----
#pragma unroll
        for (int jp = 0; jp < 4; jp++)
            mma_f16(lac[0], lac[1], lac[2], lac[3],
                    pp[2 * jp][0], pp[2 * jp][1],
                    pp[2 * jp + 1][0], pp[2 * jp + 1][1],
                    ONES2, ONES2);

        // ---- O += P V (ldmatrix.trans) ----
#pragma unroll
        for (int jp = 0; jp < 4; jp++) {
            const unsigned pa0 = pp[2 * jp][0], pa1 = pp[2 * jp][1];
            const unsigned pa2 = pp[2 * jp + 1][0], pa3 = pp[2 * jp + 1][1];
#pragma unroll
            for (int np = 0; np < 4; np++) {
                unsigned v0, v1, v2, v3;
                unsigned addr = vsb[buf] + ((jp * 16 + vrow) * KVS + np * 16 + vcol) * 2;
                asm volatile(
                    "ldmatrix.sync.aligned.m8n8.x4.trans.shared.b16 "
                    "{%0,%1,%2,%3}, [%4];"
                    : "=r"(v0), "=r"(v1), "=r"(v2), "=r"(v3) : "r"(addr));
                mma_f16(o[np * 2][0], o[np * 2][1], o[np * 2][2], o[np * 2][3],
                        pa0, pa1, pa2, pa3, v0, v1);
                mma_f16(o[np * 2 + 1][0], o[np * 2 + 1][1],
                        o[np * 2 + 1][2], o[np * 2 + 1][3],
                        pa0, pa1, pa2, pa3, v2, v3);
            }
        }
    }
#undef LOAD_KV

    {
        const float inv0 = 1.0f / lac[0];
        const float inv1 = 1.0f / lac[2];
        const int q0 = qb * 128 + wm * 16 + g;
#pragma unroll
        for (int ni = 0; ni < 8; ni++) {
            const int c = h * HD + ni * 8 + 2 * t;
            *(unsigned*)&g_O[q0 * DM + c] = pack2(o[ni][0] * inv0, o[ni][1] * inv0);
            *(unsigned*)&g_O[(q0 + 8) * DM + c] = pack2(o[ni][2] * inv1, o[ni][3] * inv1);
        }
    }
}

// ---------------------------------------------------------------------------
extern "C" void kernel_launch(void* const* d_in, const int* in_sizes, int n_in,
                              void* d_out, int out_size) {
    (void)in_sizes; (void)n_in; (void)out_size;
    const float* x  = (const float*)d_in[0];
    const float* Wq = (const float*)d_in[1];
    const float* Wk = (const float*)d_in[2];
    const float* Wv = (const float*)d_in[3];
    const float* Wo = (const float*)d_in[4];
    float* out = (float*)d_out;

    prepass_x<<<S_LEN * DM / 4 / 256, 256>>>(x);
    prepass_w<<<dim3(DM / 32, DM / 32, 4), 256>>>(Wq, Wk, Wv, Wo);

    gemm_h<1><<<dim3(DM / 128, S_LEN / 128, 3), 256>>>(nullptr);

    attn_h<<<dim3(S_LEN / 128, NH), 256>>>();

    gemm_h<0><<<dim3(DM / 128, S_LEN / 128, 1), 256>>>(out);
}